// round 12
// baseline (speedup 1.0000x reference)
#include <cuda_runtime.h>
#include <cuda_bf16.h>
#include <math.h>
#include <cstdint>

#define BB 8
#define TT 4096
#define DD 512
#define UU 768
#define LL 4
#define VV 256
#define DFFC 2048
#define MM (BB*TT)          // 32768 rows
#define NSCAN 64            // persistent scan CTAs (12 u-cols each)

typedef unsigned long long ull;

// ---------------- PTX helpers ----------------------------------------------
__device__ __forceinline__ void bar_red_release(unsigned* p) {
    asm volatile("red.release.gpu.add.u32 [%0], 1;" :: "l"(p) : "memory");
}
__device__ __forceinline__ unsigned ld_acquire(const unsigned* p) {
    unsigned v;
    asm volatile("ld.acquire.gpu.u32 %0, [%1];" : "=r"(v) : "l"(p) : "memory");
    return v;
}
__device__ __forceinline__ uint32_t smem_u32(const void* p) {
    uint32_t a;
    asm("{ .reg .u64 t; cvta.to.shared.u64 t, %1; cvt.u32.u64 %0, t; }" : "=r"(a) : "l"(p));
    return a;
}
__device__ __forceinline__ void cpa16(uint32_t s, const void* g) {
    asm volatile("cp.async.cg.shared.global [%0], [%1], 16;" :: "r"(s), "l"(g));
}
__device__ __forceinline__ void cpa_commit() {
    asm volatile("cp.async.commit_group;" ::: "memory");
}
template<int N>
__device__ __forceinline__ void cpa_wait() {
    asm volatile("cp.async.wait_group %0;" :: "n"(N) : "memory");
}
__device__ __forceinline__ void ldsm_x4(uint32_t* r, uint32_t a) {
    asm volatile("ldmatrix.sync.aligned.m8n8.x4.shared.b16 {%0,%1,%2,%3}, [%4];"
        : "=r"(r[0]), "=r"(r[1]), "=r"(r[2]), "=r"(r[3]) : "r"(a));
}
__device__ __forceinline__ void ldsm_x4t(uint32_t* r, uint32_t a) {
    asm volatile("ldmatrix.sync.aligned.m8n8.x4.trans.shared.b16 {%0,%1,%2,%3}, [%4];"
        : "=r"(r[0]), "=r"(r[1]), "=r"(r[2]), "=r"(r[3]) : "r"(a));
}
__device__ __forceinline__ void ldsm_x2t(uint32_t* r, uint32_t a) {
    asm volatile("ldmatrix.sync.aligned.m8n8.x2.trans.shared.b16 {%0,%1}, [%2];"
        : "=r"(r[0]), "=r"(r[1]) : "r"(a));
}
__device__ __forceinline__ void mma16816(float* d, const uint32_t* a, const uint32_t* b) {
    asm volatile("mma.sync.aligned.m16n8k16.row.col.f32.bf16.bf16.f32 "
        "{%0,%1,%2,%3}, {%4,%5,%6,%7}, {%8,%9}, {%0,%1,%2,%3};"
        : "+f"(d[0]), "+f"(d[1]), "+f"(d[2]), "+f"(d[3])
        : "r"(a[0]), "r"(a[1]), "r"(a[2]), "r"(a[3]), "r"(b[0]), "r"(b[1]));
}
__device__ __forceinline__ uint32_t pkbf(float v0, float v1) {
    __nv_bfloat16 h0 = __float2bfloat16(v0), h1 = __float2bfloat16(v1);
    return ((uint32_t)__bfloat16_as_ushort(h1) << 16) | __bfloat16_as_ushort(h0);
}
__device__ __forceinline__ float bflo(float v) {
    return v - __bfloat162float(__float2bfloat16(v));
}
// fast transcendentals (MUFU ex2/rcp based; rel err ~1e-6)
__device__ __forceinline__ float ftanh(float x) {
    float e = __expf(2.f*x);
    return __fdividef(e - 1.f, e + 1.f);
}
__device__ __forceinline__ float fsigm(float x) {
    return __fdividef(1.f, 1.f + __expf(-x));
}

// ---------------- scratch ---------------------------------------------------
__device__ float g_x[MM*DD];
__device__ float g_xpre[4][TT*BB*UU];
__device__ float g_cfc[MM*DD];
__device__ unsigned int g_hu[2][UU*BB];   // h as packed (bf16 hi | bf16 lo<<16), [k][b]
__device__ float g_loss[2];
__device__ unsigned int g_bar;            // monotonic across layers within a launch
__device__ __nv_bfloat16 g_ah1[MM*DD],  g_al1[MM*DD];
__device__ __nv_bfloat16 g_ah2[(size_t)MM*DFFC], g_al2[(size_t)MM*DFFC];
__device__ __nv_bfloat16 g_wh[4*DD*UU], g_wl[4*DD*UU];   // ≥ max(4*DD*UU, DFFC*DD)
__device__ __nv_bfloat16 g_wteh[VV*DD], g_wtel[VV*DD];

// ---------------- fused embed + LN1(layer0) + state reset --------------------
// 256 threads handle 2 rows (128 threads per row).
__global__ void embln_k(const int* __restrict__ idx, const float* __restrict__ wte,
                        const float* __restrict__ s, const float* __restrict__ b,
                        __nv_bfloat16* __restrict__ oh, __nv_bfloat16* __restrict__ ol) {
    __shared__ float red[2][8];
    if (blockIdx.x == 0 && threadIdx.x == 0) {
        g_bar = 0u; g_loss[0] = 0.f; g_loss[1] = 0.f;
    }
    const int half = threadIdx.x >> 7;        // 0,1
    const int wg   = threadIdx.x & 127;
    const int row  = blockIdx.x*2 + half;
    const int tok  = idx[row];
    float v[4]; float sum = 0.f, sq = 0.f;
#pragma unroll
    for (int j=0;j<4;j++) {
        v[j] = wte[(size_t)tok*DD + wg + j*128];
        g_x[(size_t)row*DD + wg + j*128] = v[j];
        sum += v[j]; sq += v[j]*v[j];
    }
#pragma unroll
    for (int off=16; off; off>>=1) {
        sum += __shfl_xor_sync(0xffffffffu, sum, off);
        sq  += __shfl_xor_sync(0xffffffffu, sq,  off);
    }
    int w = wg >> 5, lane = wg & 31;
    if (lane == 0) { red[half][w] = sum; }
    __syncthreads();
    if (lane == 1 && w == 0) {
        red[half][0] = red[half][0]+red[half][1]+red[half][2]+red[half][3];
    }
    __syncthreads();
    // second pass for sq (reuse smem)
    if (lane == 0) { red[half][4+w] = sq; }
    __syncthreads();
    if (lane == 1 && w == 0) {
        red[half][4] = red[half][4]+red[half][5]+red[half][6]+red[half][7];
    }
    __syncthreads();
    float mean = red[half][0]*(1.f/512.f);
    float var  = red[half][4]*(1.f/512.f) - mean*mean;
    float r = rsqrtf(var + 1e-5f);
#pragma unroll
    for (int j=0;j<4;j++) {
        int d = wg + j*128;
        float t = (v[j]-mean)*r*s[d] + b[d];
        __nv_bfloat16 h = __float2bfloat16(t);
        __nv_bfloat16 l = __float2bfloat16(t - __bfloat162float(h));
        oh[(size_t)row*DD + d] = h;
        ol[(size_t)row*DD + d] = l;
    }
}

// ---------------- layernorm -> bf16 hi/lo -----------------------------------
__global__ void ln_bf_k(const float* __restrict__ in, const float* __restrict__ s,
                        const float* __restrict__ b,
                        __nv_bfloat16* __restrict__ oh, __nv_bfloat16* __restrict__ ol) {
    __shared__ float red[8];
    int row = blockIdx.x;
    const float* x = in + (size_t)row*DD;
    float v[4]; float sum = 0.f, sq = 0.f;
#pragma unroll
    for (int j=0;j<4;j++) { v[j] = x[threadIdx.x + j*128]; sum += v[j]; sq += v[j]*v[j]; }
#pragma unroll
    for (int off=16; off; off>>=1) {
        sum += __shfl_xor_sync(0xffffffffu, sum, off);
        sq  += __shfl_xor_sync(0xffffffffu, sq,  off);
    }
    int w = threadIdx.x >> 5, lane = threadIdx.x & 31;
    if (lane == 0) { red[w] = sum; red[4+w] = sq; }
    __syncthreads();
    if (threadIdx.x == 0) {
        red[0] = red[0]+red[1]+red[2]+red[3];
        red[4] = red[4]+red[5]+red[6]+red[7];
    }
    __syncthreads();
    float mean = red[0]*(1.f/512.f);
    float var  = red[4]*(1.f/512.f) - mean*mean;
    float r = rsqrtf(var + 1e-5f);
#pragma unroll
    for (int j=0;j<4;j++) {
        int d = threadIdx.x + j*128;
        float t = (v[j]-mean)*r*s[d] + b[d];
        __nv_bfloat16 h = __float2bfloat16(t);
        __nv_bfloat16 l = __float2bfloat16(t - __bfloat162float(h));
        oh[(size_t)row*DD + d] = h;
        ol[(size_t)row*DD + d] = l;
    }
}

// ---------------- elementwise f32 -> bf16 hi/lo ------------------------------
__global__ void cvt_e_k(const float* __restrict__ X,
                        __nv_bfloat16* __restrict__ oh, __nv_bfloat16* __restrict__ ol) {
    int e = blockIdx.x*256 + threadIdx.x;
    float x = X[e];
    __nv_bfloat16 h = __float2bfloat16(x);
    __nv_bfloat16 l = __float2bfloat16(x - __bfloat162float(h));
    oh[e] = h; ol[e] = l;
}

// ---------------- fused 4-gate weight convert --------------------------------
__global__ void cvt4_k(const float* __restrict__ W0, const float* __restrict__ W1,
                       const float* __restrict__ W2, const float* __restrict__ W3,
                       __nv_bfloat16* __restrict__ oh, __nv_bfloat16* __restrict__ ol) {
    int e = blockIdx.x*256 + threadIdx.x;          // over 4*DD*UU
    int gate = e / (DD*UU);
    int off  = e - gate*(DD*UU);
    const float* W = (gate==0)?W0:(gate==1)?W1:(gate==2)?W2:W3;
    float x = W[off];
    __nv_bfloat16 h = __float2bfloat16(x);
    __nv_bfloat16 l = __float2bfloat16(x - __bfloat162float(h));
    oh[e] = h; ol[e] = l;
}

// ---------------- bf16x3 tensor-core GEMM (mma.sync) — R7, unchanged --------
#define STG_BYTES 32768
#define GSMEM (2*STG_BYTES)

template<int EPI, bool BTR>
__global__ void __launch_bounds__(256) mm_gemm(
    const __nv_bfloat16* __restrict__ Ah, const __nv_bfloat16* __restrict__ Al,
    const __nv_bfloat16* __restrict__ Bh, const __nv_bfloat16* __restrict__ Bl,
    const float* __restrict__ bias, const float* __restrict__ R,
    float* __restrict__ Cf, __nv_bfloat16* __restrict__ Ch, __nv_bfloat16* __restrict__ Cl,
    int N, int K)
{
    extern __shared__ char sm[];
    const uint32_t sb = smem_u32(sm);
    const int tid = threadIdx.x, wid = tid >> 5, lane = tid & 31;
    const int wm = wid & 1, wn = wid >> 1;
    const int m0 = blockIdx.y << 7, n0 = blockIdx.x << 7;

    const int arow = tid >> 1, ac0 = (tid & 1) * 2;
    const int as   = (arow >> 1) & 3;
    const uint32_t aOff0 = (uint32_t)(arow*64 + ((ac0   ^ as) & 3)*16);
    const uint32_t aOff1 = (uint32_t)(arow*64 + (((ac0+1)^ as) & 3)*16);
    const int brow = tid >> 3, bc0 = (tid & 7) * 2;
    const uint32_t bOff0 = (uint32_t)(brow*256 + (((bc0  ) & 8) | (((bc0  ) ^ (brow&7)) & 7))*16);
    const uint32_t bOff1 = (uint32_t)(brow*256 + (((bc0+1) & 8) | (((bc0+1) ^ (brow&7)) & 7))*16);

    float acc[4][4][4];
#pragma unroll
    for (int i=0;i<4;i++)
#pragma unroll
        for (int j=0;j<4;j++)
#pragma unroll
            for (int q=0;q<4;q++) acc[i][j][q] = 0.f;

    const int NC = K >> 5;

    auto load_stage = [&](int c, int st) {
        const uint32_t s0 = sb + st*STG_BYTES;
        const int k0 = c << 5;
        {
            const __nv_bfloat16* ga = Ah + (size_t)(m0 + arow)*K + k0 + ac0*8;
            cpa16(s0 + aOff0, ga);
            cpa16(s0 + aOff1, ga + 8);
            const __nv_bfloat16* gl = Al + (size_t)(m0 + arow)*K + k0 + ac0*8;
            cpa16(s0 + 8192 + aOff0, gl);
            cpa16(s0 + 8192 + aOff1, gl + 8);
        }
        if (!BTR) {
            const __nv_bfloat16* gb = Bh + (size_t)(k0 + brow)*N + n0 + bc0*8;
            cpa16(s0 + 16384 + bOff0, gb);
            cpa16(s0 + 16384 + bOff1, gb + 8);
            const __nv_bfloat16* gl = Bl + (size_t)(k0 + brow)*N + n0 + bc0*8;
            cpa16(s0 + 24576 + bOff0, gl);
            cpa16(s0 + 24576 + bOff1, gl + 8);
        } else {
            const __nv_bfloat16* gb = Bh + (size_t)(n0 + arow)*K + k0 + ac0*8;
            cpa16(s0 + 16384 + aOff0, gb);
            cpa16(s0 + 16384 + aOff1, gb + 8);
            const __nv_bfloat16* gl = Bl + (size_t)(n0 + arow)*K + k0 + ac0*8;
            cpa16(s0 + 24576 + aOff0, gl);
            cpa16(s0 + 24576 + aOff1, gl + 8);
        }
        cpa_commit();
    };

    load_stage(0, 0);
    const int mat = lane >> 3, j8 = lane & 7;

    for (int c = 0; c < NC; c++) {
        if (c + 1 < NC) load_stage(c+1, (c+1)&1);
        if (c + 1 < NC) { cpa_wait<1>(); } else { cpa_wait<0>(); }
        __syncthreads();

        const uint32_t s0 = sb + (c&1)*STG_BYTES;
        const uint32_t sAh = s0, sAl = s0 + 8192, sBh = s0 + 16384, sBl = s0 + 24576;

#pragma unroll
        for (int k16 = 0; k16 < 2; k16++) {
            uint32_t fah[4][4], fal[4][4];
#pragma unroll
            for (int mi=0;mi<4;mi++) {
                int row = wm*64 + mi*16 + (mat&1)*8 + j8;
                int cc  = (k16*2 + (mat>>1)) ^ ((row>>1)&3);
                uint32_t off = (uint32_t)(row*64 + cc*16);
                ldsm_x4(fah[mi], sAh + off);
                ldsm_x4(fal[mi], sAl + off);
            }
            uint32_t fbh[4][2], fbl[4][2];
            if (!BTR) {
#pragma unroll
                for (int bi=0;bi<2;bi++) {
                    int row = k16*16 + (mat&1)*8 + j8;
                    int cn  = wn*4 + bi*2 + (mat>>1);
                    int cc  = (cn & 8) | ((cn ^ (row&7)) & 7);
                    uint32_t off = (uint32_t)(row*256 + cc*16);
                    uint32_t r4[4];
                    ldsm_x4t(r4, sBh + off);
                    fbh[2*bi][0]=r4[0]; fbh[2*bi][1]=r4[1]; fbh[2*bi+1][0]=r4[2]; fbh[2*bi+1][1]=r4[3];
                    ldsm_x4t(r4, sBl + off);
                    fbl[2*bi][0]=r4[0]; fbl[2*bi][1]=r4[1]; fbl[2*bi+1][0]=r4[2]; fbl[2*bi+1][1]=r4[3];
                }
            } else {
#pragma unroll
                for (int bi=0;bi<2;bi++) {
                    int row = wn*32 + bi*16 + (mat>>1)*8 + j8;
                    int cc  = (k16*2 + (mat&1)) ^ ((row>>1)&3);
                    uint32_t off = (uint32_t)(row*64 + cc*16);
                    uint32_t r4[4];
                    ldsm_x4(r4, sBh + off);
                    fbh[2*bi][0]=r4[0]; fbh[2*bi][1]=r4[1]; fbh[2*bi+1][0]=r4[2]; fbh[2*bi+1][1]=r4[3];
                    ldsm_x4(r4, sBl + off);
                    fbl[2*bi][0]=r4[0]; fbl[2*bi][1]=r4[1]; fbl[2*bi+1][0]=r4[2]; fbl[2*bi+1][1]=r4[3];
                }
            }
#pragma unroll
            for (int mi=0;mi<4;mi++)
#pragma unroll
                for (int ni=0;ni<4;ni++) {
                    mma16816(acc[mi][ni], fah[mi], fbh[ni]);
                    mma16816(acc[mi][ni], fal[mi], fbh[ni]);
                    mma16816(acc[mi][ni], fah[mi], fbl[ni]);
                }
        }
        __syncthreads();
    }

    const int lr = lane >> 2, lc = (lane & 3) * 2;
#pragma unroll
    for (int mi=0;mi<4;mi++) {
#pragma unroll
        for (int hh=0;hh<2;hh++) {
            const int m = m0 + wm*64 + mi*16 + hh*8 + lr;
#pragma unroll
            for (int ni=0;ni<4;ni++) {
                const int n = n0 + wn*32 + ni*8 + lc;
                float v0 = acc[mi][ni][2*hh], v1 = acc[mi][ni][2*hh+1];
                if (EPI != 0) { v0 += bias[n]; v1 += bias[n+1]; }
                if (EPI == 1) {
                    int b_ = m >> 12, t_ = m & 4095;
                    float2* p = reinterpret_cast<float2*>(&Cf[(size_t)t_*(BB*UU) + b_*UU + n]);
                    *p = make_float2(v0, v1);
                } else if (EPI == 2) {
                    v0 = 0.5f*v0*(1.f + erff(v0*0.70710678118654752f));
                    v1 = 0.5f*v1*(1.f + erff(v1*0.70710678118654752f));
                    __nv_bfloat16 h0 = __float2bfloat16(v0);
                    __nv_bfloat16 h1 = __float2bfloat16(v1);
                    __nv_bfloat16 l0 = __float2bfloat16(v0 - __bfloat162float(h0));
                    __nv_bfloat16 l1 = __float2bfloat16(v1 - __bfloat162float(h1));
                    *reinterpret_cast<uint32_t*>(&Ch[(size_t)m*N + n]) =
                        ((uint32_t)__bfloat16_as_ushort(h1) << 16) | __bfloat16_as_ushort(h0);
                    *reinterpret_cast<uint32_t*>(&Cl[(size_t)m*N + n]) =
                        ((uint32_t)__bfloat16_as_ushort(l1) << 16) | __bfloat16_as_ushort(l0);
                } else if (EPI == 3) {
                    float2 r = *reinterpret_cast<const float2*>(&R[(size_t)m*N + n]);
                    *reinterpret_cast<float2*>(&Cf[(size_t)m*N + n]) =
                        make_float2(v0 + r.x, v1 + r.y);
                } else {
                    *reinterpret_cast<float2*>(&Cf[(size_t)m*N + n]) = make_float2(v0, v1);
                }
            }
        }
    }
}

// ---------------- fused projection GEMM (4 gates via blockIdx.z) -------------
__global__ void __launch_bounds__(256) mm_gemm_p(
    const __nv_bfloat16* __restrict__ Ah, const __nv_bfloat16* __restrict__ Al,
    const __nv_bfloat16* __restrict__ WhB, const __nv_bfloat16* __restrict__ WlB,
    const float* __restrict__ b0, const float* __restrict__ b1,
    const float* __restrict__ b2, const float* __restrict__ b3,
    float* __restrict__ xpre)
{
    extern __shared__ char sm[];
    const uint32_t sb = smem_u32(sm);
    const int tid = threadIdx.x, wid = tid >> 5, lane = tid & 31;
    const int wm = wid & 1, wn = wid >> 1;
    const int m0 = blockIdx.y << 7, n0 = blockIdx.x << 7;
    const int z  = blockIdx.z;
    const int N = UU, K = DD;
    const __nv_bfloat16* Bh = WhB + (size_t)z*DD*UU;
    const __nv_bfloat16* Bl = WlB + (size_t)z*DD*UU;
    const float* bias = (z==0)?b0:(z==1)?b1:(z==2)?b2:b3;
    float* Cf = xpre + (size_t)z*((size_t)TT*BB*UU);

    const int arow = tid >> 1, ac0 = (tid & 1) * 2;
    const int as   = (arow >> 1) & 3;
    const uint32_t aOff0 = (uint32_t)(arow*64 + ((ac0   ^ as) & 3)*16);
    const uint32_t aOff1 = (uint32_t)(arow*64 + (((ac0+1)^ as) & 3)*16);
    const int brow = tid >> 3, bc0 = (tid & 7) * 2;
    const uint32_t bOff0 = (uint32_t)(brow*256 + (((bc0  ) & 8) | (((bc0  ) ^ (brow&7)) & 7))*16);
    const uint32_t bOff1 = (uint32_t)(brow*256 + (((bc0+1) & 8) | (((bc0+1) ^ (brow&7)) & 7))*16);

    float acc[4][4][4];
#pragma unroll
    for (int i=0;i<4;i++)
#pragma unroll
        for (int j=0;j<4;j++)
#pragma unroll
            for (int q=0;q<4;q++) acc[i][j][q] = 0.f;

    const int NC = K >> 5;
    auto load_stage = [&](int c, int st) {
        const uint32_t s0 = sb + st*STG_BYTES;
        const int k0 = c << 5;
        const __nv_bfloat16* ga = Ah + (size_t)(m0 + arow)*K + k0 + ac0*8;
        cpa16(s0 + aOff0, ga);
        cpa16(s0 + aOff1, ga + 8);
        const __nv_bfloat16* gla = Al + (size_t)(m0 + arow)*K + k0 + ac0*8;
        cpa16(s0 + 8192 + aOff0, gla);
        cpa16(s0 + 8192 + aOff1, gla + 8);
        const __nv_bfloat16* gb = Bh + (size_t)(k0 + brow)*N + n0 + bc0*8;
        cpa16(s0 + 16384 + bOff0, gb);
        cpa16(s0 + 16384 + bOff1, gb + 8);
        const __nv_bfloat16* glb = Bl + (size_t)(k0 + brow)*N + n0 + bc0*8;
        cpa16(s0 + 24576 + bOff0, glb);
        cpa16(s0 + 24576 + bOff1, glb + 8);
        cpa_commit();
    };

    load_stage(0, 0);
    const int mat = lane >> 3, j8 = lane & 7;

    for (int c = 0; c < NC; c++) {
        if (c + 1 < NC) load_stage(c+1, (c+1)&1);
        if (c + 1 < NC) { cpa_wait<1>(); } else { cpa_wait<0>(); }
        __syncthreads();

        const uint32_t s0 = sb + (c&1)*STG_BYTES;
        const uint32_t sAh = s0, sAl = s0 + 8192, sBh = s0 + 16384, sBl = s0 + 24576;

#pragma unroll
        for (int k16 = 0; k16 < 2; k16++) {
            uint32_t fah[4][4], fal[4][4];
#pragma unroll
            for (int mi=0;mi<4;mi++) {
                int row = wm*64 + mi*16 + (mat&1)*8 + j8;
                int cc  = (k16*2 + (mat>>1)) ^ ((row>>1)&3);
                uint32_t off = (uint32_t)(row*64 + cc*16);
                ldsm_x4(fah[mi], sAh + off);
                ldsm_x4(fal[mi], sAl + off);
            }
            uint32_t fbh[4][2], fbl[4][2];
#pragma unroll
            for (int bi=0;bi<2;bi++) {
                int row = k16*16 + (mat&1)*8 + j8;
                int cn  = wn*4 + bi*2 + (mat>>1);
                int cc  = (cn & 8) | ((cn ^ (row&7)) & 7);
                uint32_t off = (uint32_t)(row*256 + cc*16);
                uint32_t r4[4];
                ldsm_x4t(r4, sBh + off);
                fbh[2*bi][0]=r4[0]; fbh[2*bi][1]=r4[1]; fbh[2*bi+1][0]=r4[2]; fbh[2*bi+1][1]=r4[3];
                ldsm_x4t(r4, sBl + off);
                fbl[2*bi][0]=r4[0]; fbl[2*bi][1]=r4[1]; fbl[2*bi+1][0]=r4[2]; fbl[2*bi+1][1]=r4[3];
            }
#pragma unroll
            for (int mi=0;mi<4;mi++)
#pragma unroll
                for (int ni=0;ni<4;ni++) {
                    mma16816(acc[mi][ni], fah[mi], fbh[ni]);
                    mma16816(acc[mi][ni], fal[mi], fbh[ni]);
                    mma16816(acc[mi][ni], fah[mi], fbl[ni]);
                }
        }
        __syncthreads();
    }

    const int lr = lane >> 2, lc = (lane & 3) * 2;
#pragma unroll
    for (int mi=0;mi<4;mi++) {
#pragma unroll
        for (int hh=0;hh<2;hh++) {
            const int m = m0 + wm*64 + mi*16 + hh*8 + lr;
#pragma unroll
            for (int ni=0;ni<4;ni++) {
                const int n = n0 + wn*32 + ni*8 + lc;
                float v0 = acc[mi][ni][2*hh] + bias[n];
                float v1 = acc[mi][ni][2*hh+1] + bias[n+1];
                int b_ = m >> 12, t_ = m & 4095;
                *reinterpret_cast<float2*>(&Cf[(size_t)t_*(BB*UU) + b_*UU + n]) =
                    make_float2(v0, v1);
            }
        }
    }
}

// ---------------- persistent tensor-core CfC scan (64 CTAs, 12 u each) -------
// M=48 (12u x 4 gates) = 3 m-tiles; 12 warps = mt(0..2) x ks(0..3), k-slice 192.
__global__ void __launch_bounds__(384, 1) scan_k(
    const float* __restrict__ Wh1, const float* __restrict__ Wh2,
    const float* __restrict__ Wha, const float* __restrict__ Whb,
    const float* __restrict__ x1,  const float* __restrict__ x2,
    const float* __restrict__ xa,  const float* __restrict__ xb,
    int layer)
{
    __shared__ __align__(16) __nv_bfloat16 sH[UU*8];   // h hi, [k][8]
    __shared__ __align__(16) __nv_bfloat16 sL[UU*8];   // h lo
    __shared__ float part[3][4][16][8];                // [mt][ks][m][b]

    const int tid  = threadIdx.x;
    const int wid  = tid >> 5, lane = tid & 31;
    const int mt   = wid % 3, ks = wid / 3;            // mt 0..2, ks 0..3
    const int ublk = blockIdx.x * 12;
    const int g    = lane >> 2, tg = lane & 3;
    const uint32_t sHb = smem_u32(sH), sLb = smem_u32(sL);
    const unsigned tbase = (unsigned)layer * TT * NSCAN;

    // ---- load W fragments into registers (once) ----
    const float* Wg4[4] = {Wh1, Wh2, Wha, Whb};
    const float* Wm = Wg4[g & 3];
    const int u0 = ublk + ((mt*16 + g)     >> 2);
    const int u1 = ublk + ((mt*16 + g + 8) >> 2);
    uint32_t Afh[12][4], Afl[12][4];
#pragma unroll
    for (int j=0;j<12;j++) {
        const int kb = ks*192 + j*16 + tg*2;
        float w00 = Wm[(size_t)(kb  )*UU + u0], w01 = Wm[(size_t)(kb+1)*UU + u0];
        float w10 = Wm[(size_t)(kb  )*UU + u1], w11 = Wm[(size_t)(kb+1)*UU + u1];
        float w20 = Wm[(size_t)(kb+8)*UU + u0], w21 = Wm[(size_t)(kb+9)*UU + u0];
        float w30 = Wm[(size_t)(kb+8)*UU + u1], w31 = Wm[(size_t)(kb+9)*UU + u1];
        Afh[j][0] = pkbf(w00, w01); Afl[j][0] = pkbf(bflo(w00), bflo(w01));
        Afh[j][1] = pkbf(w10, w11); Afl[j][1] = pkbf(bflo(w10), bflo(w11));
        Afh[j][2] = pkbf(w20, w21); Afl[j][2] = pkbf(bflo(w20), bflo(w21));
        Afh[j][3] = pkbf(w30, w31); Afl[j][3] = pkbf(bflo(w30), bflo(w31));
    }

    // finalize mapping (tid < 96): (u-local 0..11, batch 0..7)
    const int ful = tid >> 3, fB = tid & 7;
    const int fmt = ful >> 2, frb = (ful & 3) * 4;
    const int fug = ublk + ful;

    // prefetch xpre for t=0
    float p1=0.f, p2=0.f, pa4=0.f, pb4=0.f;
    if (tid < 96) {
        int xi = fB*UU + fug;
        p1 = x1[xi]; p2 = x2[xi]; pa4 = xa[xi]; pb4 = xb[xi];
    }

    const int r0 = tid*2;

    for (int t = 0; t < TT; t++) {
        // ---- stage h into smem (hi/lo split) ----
        if (t == 0) {
            uint4 z = make_uint4(0,0,0,0);
            *reinterpret_cast<uint4*>(&sH[r0*8])     = z;
            *reinterpret_cast<uint4*>(&sH[(r0+1)*8]) = z;
            *reinterpret_cast<uint4*>(&sL[r0*8])     = z;
            *reinterpret_cast<uint4*>(&sL[(r0+1)*8]) = z;
        } else {
            const uint4* gp = reinterpret_cast<const uint4*>(&g_hu[t & 1][0]);
#pragma unroll
            for (int rr=0; rr<2; rr++) {
                uint4 q0 = __ldcg(gp + (r0+rr)*2);
                uint4 q1 = __ldcg(gp + (r0+rr)*2 + 1);
                uint4 hi, lo;
                hi.x = __byte_perm(q0.x, q0.y, 0x5410); hi.y = __byte_perm(q0.z, q0.w, 0x5410);
                hi.z = __byte_perm(q1.x, q1.y, 0x5410); hi.w = __byte_perm(q1.z, q1.w, 0x5410);
                lo.x = __byte_perm(q0.x, q0.y, 0x7632); lo.y = __byte_perm(q0.z, q0.w, 0x7632);
                lo.z = __byte_perm(q1.x, q1.y, 0x7632); lo.w = __byte_perm(q1.z, q1.w, 0x7632);
                *reinterpret_cast<uint4*>(&sH[(r0+rr)*8]) = hi;
                *reinterpret_cast<uint4*>(&sL[(r0+rr)*8]) = lo;
            }
        }
        __syncthreads();

        // ---- MMA phase: 3 independent accumulator chains ----
        float ac0[4] = {0.f,0.f,0.f,0.f};
        float ac1[4] = {0.f,0.f,0.f,0.f};
        float ac2[4] = {0.f,0.f,0.f,0.f};
        const int krow = ks*192 + (lane & 15);
#pragma unroll
        for (int j=0;j<12;j++) {
            uint32_t bh[2], bl[2];
            uint32_t off = (uint32_t)((krow + j*16) * 16);
            ldsm_x2t(bh, sHb + off);
            ldsm_x2t(bl, sLb + off);
            mma16816(ac0, Afh[j], bh);
            mma16816(ac1, Afl[j], bh);
            mma16816(ac2, Afh[j], bl);
        }
        float acc[4];
#pragma unroll
        for (int q=0;q<4;q++) acc[q] = (ac0[q] + ac1[q]) + ac2[q];
        *reinterpret_cast<float2*>(&part[mt][ks][g][tg*2])   = make_float2(acc[0], acc[1]);
        *reinterpret_cast<float2*>(&part[mt][ks][g+8][tg*2]) = make_float2(acc[2], acc[3]);
        __syncthreads();

        // ---- finalize (96 threads) + release + hidden work + poll ----
        if (tid < 96) {
            float s0=0.f, s1=0.f, s2=0.f, s3=0.f;
#pragma unroll
            for (int k4=0;k4<4;k4++) {
                s0 += part[fmt][k4][frb+0][fB];
                s1 += part[fmt][k4][frb+1][fB];
                s2 += part[fmt][k4][frb+2][fB];
                s3 += part[fmt][k4][frb+3][fB];
            }
            float f1 = ftanh(s0 + p1), f2 = ftanh(s1 + p2);
            float ti = fsigm(s2 + pa4 + s3 + pb4);
            float hn = f1 + ti*(f2 - f1);
            float hl = bflo(hn);
            unsigned pk = ((uint32_t)__bfloat16_as_ushort(__float2bfloat16(hl)) << 16)
                        | __bfloat16_as_ushort(__float2bfloat16(hn));
            unsigned* dst = &g_hu[1-(t&1)][fug*8 + fB];
            asm volatile("st.global.cg.u32 [%0], %1;" :: "l"(dst), "r"(pk) : "memory");
            asm volatile("bar.sync 1, 96;" ::: "memory");   // all 96 h stores issued
            if (tid == 0) bar_red_release(&g_bar);
            // hidden under other CTAs' arrival:
            if (fug < DD) g_cfc[((size_t)fB*TT + t)*DD + fug] = hn;
            if (t+1 < TT) {
                int xi = (t+1)*(BB*UU) + fB*UU + fug;
                p1 = x1[xi]; p2 = x2[xi]; pa4 = xa[xi]; pb4 = xb[xi];
            }
            if (tid == 0 && t+1 < TT) {
                unsigned target = tbase + (unsigned)(t+1)*NSCAN;
                while (ld_acquire(&g_bar) < target) {}
            }
        }
        __syncthreads();
    }
}

// ---------------- LIF gate + residual add -----------------------------------
__global__ void lif_k(const float* __restrict__ thr_p,
                      const float* __restrict__ leak_p,
                      const float* __restrict__ steep_p) {
    int e = blockIdx.x*256 + threadIdx.x;
    int d = e & 511;
    float thr  = fabsf(thr_p[d]) * 0.1f;
    float leak = 1.f/(1.f + expf(-leak_p[d]));
    float sv = steep_p[d];
    float steep = (sv > 20.f) ? sv : log1pf(expf(sv));
    float c = g_cfc[e];
    float fire = 1.f/(1.f + expf(-steep*(fabsf(c) - thr)));
    float gate = fire + leak*(1.f - fire);
    g_x[e] += c*gate;
}

// ---------------- loss -------------------------------------------------------
__global__ void loss_k(const int* __restrict__ tgt, const float* __restrict__ logits) {
    int row  = blockIdx.x*8 + (threadIdx.x >> 5);
    int lane = threadIdx.x & 31;
    const float* lr = logits + (size_t)row*VV;
    float v[8]; float mx = -3.4e38f;
#pragma unroll
    for (int j=0;j<8;j++) { v[j] = lr[lane + 32*j]; mx = fmaxf(mx, v[j]); }
#pragma unroll
    for (int off=16; off; off>>=1) mx = fmaxf(mx, __shfl_xor_sync(0xffffffffu, mx, off));
    float se = 0.f;
#pragma unroll
    for (int j=0;j<8;j++) se += expf(v[j]-mx);
#pragma unroll
    for (int off=16; off; off>>=1) se += __shfl_xor_sync(0xffffffffu, se, off);
    if (lane == 0) {
        int tv = tgt[row];
        if (tv >= 0) {
            float nll = mx + logf(se) - lr[tv];
            atomicAdd(&g_loss[0], nll);
            atomicAdd(&g_loss[1], 1.f);
        }
    }
}

__global__ void fin_k(float* __restrict__ out, int out_size) {
    if (out_size > MM*VV) out[MM*VV] = g_loss[0]/g_loss[1];
}

// ---------------- driver ------------------------------------------------------
extern "C" void kernel_launch(void* const* d_in, const int* in_sizes, int n_in,
                              void* d_out, int out_size) {
    (void)in_sizes; (void)n_in;
    const int*   idx      = (const int*)  d_in[0];
    const int*   targets  = (const int*)  d_in[1];
    const float* wte      = (const float*)d_in[2];
    const float* ln1_s    = (const float*)d_in[3];
    const float* ln1_b    = (const float*)d_in[4];
    const float* Wff1     = (const float*)d_in[5];
    const float* bff1     = (const float*)d_in[6];
    const float* Wff2     = (const float*)d_in[7];
    const float* bff2     = (const float*)d_in[8];
    const float* Wta      = (const float*)d_in[9];
    const float* bta      = (const float*)d_in[10];
    const float* Wtb      = (const float*)d_in[11];
    const float* btb      = (const float*)d_in[12];
    const float* lif_thr  = (const float*)d_in[13];
    const float* lif_leak = (const float*)d_in[14];
    const float* lif_stp  = (const float*)d_in[15];
    const float* ln2_s    = (const float*)d_in[16];
    const float* ln2_b    = (const float*)d_in[17];
    const float* mW1      = (const float*)d_in[18];
    const float* mb1      = (const float*)d_in[19];
    const float* mW2      = (const float*)d_in[20];
    const float* mb2      = (const float*)d_in[21];
    const float* lnf_s    = (const float*)d_in[22];
    const float* lnf_b    = (const float*)d_in[23];
    float* out = (float*)d_out;

    cudaFuncSetAttribute(mm_gemm<0,true>,  cudaFuncAttributeMaxDynamicSharedMemorySize, GSMEM);
    cudaFuncSetAttribute(mm_gemm<2,false>, cudaFuncAttributeMaxDynamicSharedMemorySize, GSMEM);
    cudaFuncSetAttribute(mm_gemm<3,false>, cudaFuncAttributeMaxDynamicSharedMemorySize, GSMEM);
    cudaFuncSetAttribute(mm_gemm_p,        cudaFuncAttributeMaxDynamicSharedMemorySize, GSMEM);

    float *xp, *xpre;
    __nv_bfloat16 *ah1, *al1, *ah2, *al2, *wh, *wl, *wteh, *wtel;
    cudaGetSymbolAddress((void**)&xp,   g_x);
    cudaGetSymbolAddress((void**)&xpre, g_xpre);
    cudaGetSymbolAddress((void**)&ah1,  g_ah1);
    cudaGetSymbolAddress((void**)&al1,  g_al1);
    cudaGetSymbolAddress((void**)&ah2,  g_ah2);
    cudaGetSymbolAddress((void**)&al2,  g_al2);
    cudaGetSymbolAddress((void**)&wh,   g_wh);
    cudaGetSymbolAddress((void**)&wl,   g_wl);
    cudaGetSymbolAddress((void**)&wteh, g_wteh);
    cudaGetSymbolAddress((void**)&wtel, g_wtel);

    const size_t WSTRIDE = (size_t)(DD+UU)*UU;
    const size_t XG = (size_t)TT*BB*UU;

    for (int l = 0; l < LL; l++) {
        if (l == 0) {
            // launch 1: fused embed + LN1 + state reset
            embln_k<<<MM/2, 256>>>(idx, wte, ln1_s, ln1_b, ah1, al1);
        } else {
            ln_bf_k<<<MM,128>>>(xp, ln1_s + l*DD, ln1_b + l*DD, ah1, al1);
        }
        cvt4_k<<<4*DD*UU/256, 256>>>(                                    // launch 2
            Wff1 + (size_t)l*WSTRIDE, Wff2 + (size_t)l*WSTRIDE,
            Wta  + (size_t)l*WSTRIDE, Wtb  + (size_t)l*WSTRIDE, wh, wl);
        mm_gemm_p<<<dim3(UU/128, MM/128, 4), 256, GSMEM>>>(              // launch 3
            ah1, al1, wh, wl,
            bff1 + l*UU, bff2 + l*UU, bta + l*UU, btb + l*UU, xpre);

        scan_k<<<NSCAN, 384>>>(                                          // launch 4 (ncu)
            Wff1 + (size_t)l*WSTRIDE + (size_t)DD*UU,
            Wff2 + (size_t)l*WSTRIDE + (size_t)DD*UU,
            Wta  + (size_t)l*WSTRIDE + (size_t)DD*UU,
            Wtb  + (size_t)l*WSTRIDE + (size_t)DD*UU,
            xpre, xpre + XG, xpre + 2*XG, xpre + 3*XG, l);

        lif_k<<<MM*DD/256, 256>>>(lif_thr + l*DD, lif_leak + l*DD, lif_stp + l*DD);

        ln_bf_k<<<MM,128>>>(xp, ln2_s + l*DD, ln2_b + l*DD, ah1, al1);
        cvt_e_k<<<DD*DFFC/256, 256>>>(mW1 + (size_t)l*DD*DFFC, wh, wl);
        mm_gemm<2,false><<<dim3(DFFC/128, MM/128), 256, GSMEM>>>(
            ah1, al1, wh, wl, mb1 + l*DFFC, nullptr,
            nullptr, ah2, al2, DFFC, DD);
        cvt_e_k<<<DFFC*DD/256, 256>>>(mW2 + (size_t)l*DFFC*DD, wh, wl);
        mm_gemm<3,false><<<dim3(DD/128, MM/128), 256, GSMEM>>>(
            ah2, al2, wh, wl, mb2 + l*DD, xp,
            xp, nullptr, nullptr, DD, DFFC);
    }

    ln_bf_k<<<MM,128>>>(xp, lnf_s, lnf_b, ah1, al1);
    cvt_e_k<<<VV*DD/256, 256>>>(wte, wteh, wtel);
    mm_gemm<0,true><<<dim3(VV/128, MM/128), 256, GSMEM>>>(
        ah1, al1, wteh, wtel, nullptr, nullptr,
        out, nullptr, nullptr, VV, DD);
    loss_k<<<MM/8, 256>>>(targets, out);
    fin_k<<<1,1>>>(out, out_size);
}

// round 13
// speedup vs baseline: 1.0586x; 1.0586x over previous
#include <cuda_runtime.h>
#include <cuda_bf16.h>
#include <math.h>
#include <cstdint>

#define BB 8
#define TT 4096
#define DD 512
#define UU 768
#define LL 4
#define VV 256
#define DFFC 2048
#define MM (BB*TT)          // 32768 rows
#define NSCAN 96            // persistent scan CTAs (8 u-cols each)

typedef unsigned long long ull;

// ---------------- PTX helpers ----------------------------------------------
__device__ __forceinline__ void bar_red_release(unsigned* p) {
    asm volatile("red.release.gpu.add.u32 [%0], 1;" :: "l"(p) : "memory");
}
__device__ __forceinline__ unsigned ld_acquire(const unsigned* p) {
    unsigned v;
    asm volatile("ld.acquire.gpu.u32 %0, [%1];" : "=r"(v) : "l"(p) : "memory");
    return v;
}
__device__ __forceinline__ uint32_t smem_u32(const void* p) {
    uint32_t a;
    asm("{ .reg .u64 t; cvta.to.shared.u64 t, %1; cvt.u32.u64 %0, t; }" : "=r"(a) : "l"(p));
    return a;
}
__device__ __forceinline__ void cpa16(uint32_t s, const void* g) {
    asm volatile("cp.async.cg.shared.global [%0], [%1], 16;" :: "r"(s), "l"(g));
}
__device__ __forceinline__ void cpa_commit() {
    asm volatile("cp.async.commit_group;" ::: "memory");
}
template<int N>
__device__ __forceinline__ void cpa_wait() {
    asm volatile("cp.async.wait_group %0;" :: "n"(N) : "memory");
}
__device__ __forceinline__ void ldsm_x4(uint32_t* r, uint32_t a) {
    asm volatile("ldmatrix.sync.aligned.m8n8.x4.shared.b16 {%0,%1,%2,%3}, [%4];"
        : "=r"(r[0]), "=r"(r[1]), "=r"(r[2]), "=r"(r[3]) : "r"(a));
}
__device__ __forceinline__ void ldsm_x4t(uint32_t* r, uint32_t a) {
    asm volatile("ldmatrix.sync.aligned.m8n8.x4.trans.shared.b16 {%0,%1,%2,%3}, [%4];"
        : "=r"(r[0]), "=r"(r[1]), "=r"(r[2]), "=r"(r[3]) : "r"(a));
}
__device__ __forceinline__ void ldsm_x2t(uint32_t* r, uint32_t a) {
    asm volatile("ldmatrix.sync.aligned.m8n8.x2.trans.shared.b16 {%0,%1}, [%2];"
        : "=r"(r[0]), "=r"(r[1]) : "r"(a));
}
__device__ __forceinline__ void mma16816(float* d, const uint32_t* a, const uint32_t* b) {
    asm volatile("mma.sync.aligned.m16n8k16.row.col.f32.bf16.bf16.f32 "
        "{%0,%1,%2,%3}, {%4,%5,%6,%7}, {%8,%9}, {%0,%1,%2,%3};"
        : "+f"(d[0]), "+f"(d[1]), "+f"(d[2]), "+f"(d[3])
        : "r"(a[0]), "r"(a[1]), "r"(a[2]), "r"(a[3]), "r"(b[0]), "r"(b[1]));
}
__device__ __forceinline__ uint32_t pkbf(float v0, float v1) {
    __nv_bfloat16 h0 = __float2bfloat16(v0), h1 = __float2bfloat16(v1);
    return ((uint32_t)__bfloat16_as_ushort(h1) << 16) | __bfloat16_as_ushort(h0);
}
__device__ __forceinline__ float bflo(float v) {
    return v - __bfloat162float(__float2bfloat16(v));
}
// fast transcendentals (MUFU ex2/rcp based; rel err ~1e-6)
__device__ __forceinline__ float ftanh(float x) {
    float e = __expf(2.f*x);
    return __fdividef(e - 1.f, e + 1.f);
}
__device__ __forceinline__ float fsigm(float x) {
    return __fdividef(1.f, 1.f + __expf(-x));
}

// ---------------- scratch ---------------------------------------------------
__device__ float g_x[MM*DD];
__device__ float g_xpre[3][TT*BB*UU];     // x1, x2, xab (fused a+b)
__device__ float g_cfc[MM*DD];
__device__ unsigned int g_hu[2][UU*BB];   // h as packed (bf16 hi | bf16 lo<<16), [k][b]
__device__ float g_loss[2];
__device__ unsigned int g_bar;            // monotonic across layers within a launch
__device__ __nv_bfloat16 g_ah1[MM*DD],  g_al1[MM*DD];
__device__ __nv_bfloat16 g_ah2[(size_t)MM*DFFC], g_al2[(size_t)MM*DFFC];
__device__ __nv_bfloat16 g_wh[4*DD*UU], g_wl[4*DD*UU];   // ≥ max(3*DD*UU, DFFC*DD)
__device__ __nv_bfloat16 g_wteh[VV*DD], g_wtel[VV*DD];

// ---------------- fused embed + LN1(layer0) + state reset --------------------
__global__ void embln_k(const int* __restrict__ idx, const float* __restrict__ wte,
                        const float* __restrict__ s, const float* __restrict__ b,
                        __nv_bfloat16* __restrict__ oh, __nv_bfloat16* __restrict__ ol) {
    __shared__ float red[2][8];
    if (blockIdx.x == 0 && threadIdx.x == 0) {
        g_bar = 0u; g_loss[0] = 0.f; g_loss[1] = 0.f;
    }
    const int half = threadIdx.x >> 7;
    const int wg   = threadIdx.x & 127;
    const int row  = blockIdx.x*2 + half;
    const int tok  = idx[row];
    float v[4]; float sum = 0.f, sq = 0.f;
#pragma unroll
    for (int j=0;j<4;j++) {
        v[j] = wte[(size_t)tok*DD + wg + j*128];
        g_x[(size_t)row*DD + wg + j*128] = v[j];
        sum += v[j]; sq += v[j]*v[j];
    }
#pragma unroll
    for (int off=16; off; off>>=1) {
        sum += __shfl_xor_sync(0xffffffffu, sum, off);
        sq  += __shfl_xor_sync(0xffffffffu, sq,  off);
    }
    int w = wg >> 5, lane = wg & 31;
    if (lane == 0) { red[half][w] = sum; }
    __syncthreads();
    if (lane == 1 && w == 0) {
        red[half][0] = red[half][0]+red[half][1]+red[half][2]+red[half][3];
    }
    __syncthreads();
    if (lane == 0) { red[half][4+w] = sq; }
    __syncthreads();
    if (lane == 1 && w == 0) {
        red[half][4] = red[half][4]+red[half][5]+red[half][6]+red[half][7];
    }
    __syncthreads();
    float mean = red[half][0]*(1.f/512.f);
    float var  = red[half][4]*(1.f/512.f) - mean*mean;
    float r = rsqrtf(var + 1e-5f);
#pragma unroll
    for (int j=0;j<4;j++) {
        int d = wg + j*128;
        float t = (v[j]-mean)*r*s[d] + b[d];
        __nv_bfloat16 h = __float2bfloat16(t);
        __nv_bfloat16 l = __float2bfloat16(t - __bfloat162float(h));
        oh[(size_t)row*DD + d] = h;
        ol[(size_t)row*DD + d] = l;
    }
}

// ---------------- layernorm -> bf16 hi/lo -----------------------------------
__global__ void ln_bf_k(const float* __restrict__ in, const float* __restrict__ s,
                        const float* __restrict__ b,
                        __nv_bfloat16* __restrict__ oh, __nv_bfloat16* __restrict__ ol) {
    __shared__ float red[8];
    int row = blockIdx.x;
    const float* x = in + (size_t)row*DD;
    float v[4]; float sum = 0.f, sq = 0.f;
#pragma unroll
    for (int j=0;j<4;j++) { v[j] = x[threadIdx.x + j*128]; sum += v[j]; sq += v[j]*v[j]; }
#pragma unroll
    for (int off=16; off; off>>=1) {
        sum += __shfl_xor_sync(0xffffffffu, sum, off);
        sq  += __shfl_xor_sync(0xffffffffu, sq,  off);
    }
    int w = threadIdx.x >> 5, lane = threadIdx.x & 31;
    if (lane == 0) { red[w] = sum; red[4+w] = sq; }
    __syncthreads();
    if (threadIdx.x == 0) {
        red[0] = red[0]+red[1]+red[2]+red[3];
        red[4] = red[4]+red[5]+red[6]+red[7];
    }
    __syncthreads();
    float mean = red[0]*(1.f/512.f);
    float var  = red[4]*(1.f/512.f) - mean*mean;
    float r = rsqrtf(var + 1e-5f);
#pragma unroll
    for (int j=0;j<4;j++) {
        int d = threadIdx.x + j*128;
        float t = (v[j]-mean)*r*s[d] + b[d];
        __nv_bfloat16 h = __float2bfloat16(t);
        __nv_bfloat16 l = __float2bfloat16(t - __bfloat162float(h));
        oh[(size_t)row*DD + d] = h;
        ol[(size_t)row*DD + d] = l;
    }
}

// ---------------- elementwise f32 -> bf16 hi/lo ------------------------------
__global__ void cvt_e_k(const float* __restrict__ X,
                        __nv_bfloat16* __restrict__ oh, __nv_bfloat16* __restrict__ ol) {
    int e = blockIdx.x*256 + threadIdx.x;
    float x = X[e];
    __nv_bfloat16 h = __float2bfloat16(x);
    __nv_bfloat16 l = __float2bfloat16(x - __bfloat162float(h));
    oh[e] = h; ol[e] = l;
}

// ---------------- fused 3-gate weight convert (gate2 = Wta+Wtb) --------------
__global__ void cvt3_k(const float* __restrict__ W0, const float* __restrict__ W1,
                       const float* __restrict__ W2a, const float* __restrict__ W2b,
                       __nv_bfloat16* __restrict__ oh, __nv_bfloat16* __restrict__ ol) {
    int e = blockIdx.x*256 + threadIdx.x;          // over 3*DD*UU
    int gate = e / (DD*UU);
    int off  = e - gate*(DD*UU);
    float x = (gate==0) ? W0[off] : (gate==1) ? W1[off] : (W2a[off] + W2b[off]);
    __nv_bfloat16 h = __float2bfloat16(x);
    __nv_bfloat16 l = __float2bfloat16(x - __bfloat162float(h));
    oh[e] = h; ol[e] = l;
}

// ---------------- bf16x3 tensor-core GEMM (mma.sync) — R7, unchanged --------
#define STG_BYTES 32768
#define GSMEM (2*STG_BYTES)

template<int EPI, bool BTR>
__global__ void __launch_bounds__(256) mm_gemm(
    const __nv_bfloat16* __restrict__ Ah, const __nv_bfloat16* __restrict__ Al,
    const __nv_bfloat16* __restrict__ Bh, const __nv_bfloat16* __restrict__ Bl,
    const float* __restrict__ bias, const float* __restrict__ R,
    float* __restrict__ Cf, __nv_bfloat16* __restrict__ Ch, __nv_bfloat16* __restrict__ Cl,
    int N, int K)
{
    extern __shared__ char sm[];
    const uint32_t sb = smem_u32(sm);
    const int tid = threadIdx.x, wid = tid >> 5, lane = tid & 31;
    const int wm = wid & 1, wn = wid >> 1;
    const int m0 = blockIdx.y << 7, n0 = blockIdx.x << 7;

    const int arow = tid >> 1, ac0 = (tid & 1) * 2;
    const int as   = (arow >> 1) & 3;
    const uint32_t aOff0 = (uint32_t)(arow*64 + ((ac0   ^ as) & 3)*16);
    const uint32_t aOff1 = (uint32_t)(arow*64 + (((ac0+1)^ as) & 3)*16);
    const int brow = tid >> 3, bc0 = (tid & 7) * 2;
    const uint32_t bOff0 = (uint32_t)(brow*256 + (((bc0  ) & 8) | (((bc0  ) ^ (brow&7)) & 7))*16);
    const uint32_t bOff1 = (uint32_t)(brow*256 + (((bc0+1) & 8) | (((bc0+1) ^ (brow&7)) & 7))*16);

    float acc[4][4][4];
#pragma unroll
    for (int i=0;i<4;i++)
#pragma unroll
        for (int j=0;j<4;j++)
#pragma unroll
            for (int q=0;q<4;q++) acc[i][j][q] = 0.f;

    const int NC = K >> 5;

    auto load_stage = [&](int c, int st) {
        const uint32_t s0 = sb + st*STG_BYTES;
        const int k0 = c << 5;
        {
            const __nv_bfloat16* ga = Ah + (size_t)(m0 + arow)*K + k0 + ac0*8;
            cpa16(s0 + aOff0, ga);
            cpa16(s0 + aOff1, ga + 8);
            const __nv_bfloat16* gl = Al + (size_t)(m0 + arow)*K + k0 + ac0*8;
            cpa16(s0 + 8192 + aOff0, gl);
            cpa16(s0 + 8192 + aOff1, gl + 8);
        }
        if (!BTR) {
            const __nv_bfloat16* gb = Bh + (size_t)(k0 + brow)*N + n0 + bc0*8;
            cpa16(s0 + 16384 + bOff0, gb);
            cpa16(s0 + 16384 + bOff1, gb + 8);
            const __nv_bfloat16* gl = Bl + (size_t)(k0 + brow)*N + n0 + bc0*8;
            cpa16(s0 + 24576 + bOff0, gl);
            cpa16(s0 + 24576 + bOff1, gl + 8);
        } else {
            const __nv_bfloat16* gb = Bh + (size_t)(n0 + arow)*K + k0 + ac0*8;
            cpa16(s0 + 16384 + aOff0, gb);
            cpa16(s0 + 16384 + aOff1, gb + 8);
            const __nv_bfloat16* gl = Bl + (size_t)(n0 + arow)*K + k0 + ac0*8;
            cpa16(s0 + 24576 + aOff0, gl);
            cpa16(s0 + 24576 + aOff1, gl + 8);
        }
        cpa_commit();
    };

    load_stage(0, 0);
    const int mat = lane >> 3, j8 = lane & 7;

    for (int c = 0; c < NC; c++) {
        if (c + 1 < NC) load_stage(c+1, (c+1)&1);
        if (c + 1 < NC) { cpa_wait<1>(); } else { cpa_wait<0>(); }
        __syncthreads();

        const uint32_t s0 = sb + (c&1)*STG_BYTES;
        const uint32_t sAh = s0, sAl = s0 + 8192, sBh = s0 + 16384, sBl = s0 + 24576;

#pragma unroll
        for (int k16 = 0; k16 < 2; k16++) {
            uint32_t fah[4][4], fal[4][4];
#pragma unroll
            for (int mi=0;mi<4;mi++) {
                int row = wm*64 + mi*16 + (mat&1)*8 + j8;
                int cc  = (k16*2 + (mat>>1)) ^ ((row>>1)&3);
                uint32_t off = (uint32_t)(row*64 + cc*16);
                ldsm_x4(fah[mi], sAh + off);
                ldsm_x4(fal[mi], sAl + off);
            }
            uint32_t fbh[4][2], fbl[4][2];
            if (!BTR) {
#pragma unroll
                for (int bi=0;bi<2;bi++) {
                    int row = k16*16 + (mat&1)*8 + j8;
                    int cn  = wn*4 + bi*2 + (mat>>1);
                    int cc  = (cn & 8) | ((cn ^ (row&7)) & 7);
                    uint32_t off = (uint32_t)(row*256 + cc*16);
                    uint32_t r4[4];
                    ldsm_x4t(r4, sBh + off);
                    fbh[2*bi][0]=r4[0]; fbh[2*bi][1]=r4[1]; fbh[2*bi+1][0]=r4[2]; fbh[2*bi+1][1]=r4[3];
                    ldsm_x4t(r4, sBl + off);
                    fbl[2*bi][0]=r4[0]; fbl[2*bi][1]=r4[1]; fbl[2*bi+1][0]=r4[2]; fbl[2*bi+1][1]=r4[3];
                }
            } else {
#pragma unroll
                for (int bi=0;bi<2;bi++) {
                    int row = wn*32 + bi*16 + (mat>>1)*8 + j8;
                    int cc  = (k16*2 + (mat&1)) ^ ((row>>1)&3);
                    uint32_t off = (uint32_t)(row*64 + cc*16);
                    uint32_t r4[4];
                    ldsm_x4(r4, sBh + off);
                    fbh[2*bi][0]=r4[0]; fbh[2*bi][1]=r4[1]; fbh[2*bi+1][0]=r4[2]; fbh[2*bi+1][1]=r4[3];
                    ldsm_x4(r4, sBl + off);
                    fbl[2*bi][0]=r4[0]; fbl[2*bi][1]=r4[1]; fbl[2*bi+1][0]=r4[2]; fbl[2*bi+1][1]=r4[3];
                }
            }
#pragma unroll
            for (int mi=0;mi<4;mi++)
#pragma unroll
                for (int ni=0;ni<4;ni++) {
                    mma16816(acc[mi][ni], fah[mi], fbh[ni]);
                    mma16816(acc[mi][ni], fal[mi], fbh[ni]);
                    mma16816(acc[mi][ni], fah[mi], fbl[ni]);
                }
        }
        __syncthreads();
    }

    const int lr = lane >> 2, lc = (lane & 3) * 2;
#pragma unroll
    for (int mi=0;mi<4;mi++) {
#pragma unroll
        for (int hh=0;hh<2;hh++) {
            const int m = m0 + wm*64 + mi*16 + hh*8 + lr;
#pragma unroll
            for (int ni=0;ni<4;ni++) {
                const int n = n0 + wn*32 + ni*8 + lc;
                float v0 = acc[mi][ni][2*hh], v1 = acc[mi][ni][2*hh+1];
                if (EPI != 0) { v0 += bias[n]; v1 += bias[n+1]; }
                if (EPI == 2) {
                    v0 = 0.5f*v0*(1.f + erff(v0*0.70710678118654752f));
                    v1 = 0.5f*v1*(1.f + erff(v1*0.70710678118654752f));
                    __nv_bfloat16 h0 = __float2bfloat16(v0);
                    __nv_bfloat16 h1 = __float2bfloat16(v1);
                    __nv_bfloat16 l0 = __float2bfloat16(v0 - __bfloat162float(h0));
                    __nv_bfloat16 l1 = __float2bfloat16(v1 - __bfloat162float(h1));
                    *reinterpret_cast<uint32_t*>(&Ch[(size_t)m*N + n]) =
                        ((uint32_t)__bfloat16_as_ushort(h1) << 16) | __bfloat16_as_ushort(h0);
                    *reinterpret_cast<uint32_t*>(&Cl[(size_t)m*N + n]) =
                        ((uint32_t)__bfloat16_as_ushort(l1) << 16) | __bfloat16_as_ushort(l0);
                } else if (EPI == 3) {
                    float2 r = *reinterpret_cast<const float2*>(&R[(size_t)m*N + n]);
                    *reinterpret_cast<float2*>(&Cf[(size_t)m*N + n]) =
                        make_float2(v0 + r.x, v1 + r.y);
                } else {
                    *reinterpret_cast<float2*>(&Cf[(size_t)m*N + n]) = make_float2(v0, v1);
                }
            }
        }
    }
}

// ---------------- fused projection GEMM (3 gates via blockIdx.z) -------------
__global__ void __launch_bounds__(256) mm_gemm_p(
    const __nv_bfloat16* __restrict__ Ah, const __nv_bfloat16* __restrict__ Al,
    const __nv_bfloat16* __restrict__ WhB, const __nv_bfloat16* __restrict__ WlB,
    const float* __restrict__ b0, const float* __restrict__ b1,
    const float* __restrict__ b2a, const float* __restrict__ b2b,
    float* __restrict__ xpre)
{
    extern __shared__ char sm[];
    const uint32_t sb = smem_u32(sm);
    const int tid = threadIdx.x, wid = tid >> 5, lane = tid & 31;
    const int wm = wid & 1, wn = wid >> 1;
    const int m0 = blockIdx.y << 7, n0 = blockIdx.x << 7;
    const int z  = blockIdx.z;
    const int N = UU, K = DD;
    const __nv_bfloat16* Bh = WhB + (size_t)z*DD*UU;
    const __nv_bfloat16* Bl = WlB + (size_t)z*DD*UU;
    float* Cf = xpre + (size_t)z*((size_t)TT*BB*UU);

    const int arow = tid >> 1, ac0 = (tid & 1) * 2;
    const int as   = (arow >> 1) & 3;
    const uint32_t aOff0 = (uint32_t)(arow*64 + ((ac0   ^ as) & 3)*16);
    const uint32_t aOff1 = (uint32_t)(arow*64 + (((ac0+1)^ as) & 3)*16);
    const int brow = tid >> 3, bc0 = (tid & 7) * 2;
    const uint32_t bOff0 = (uint32_t)(brow*256 + (((bc0  ) & 8) | (((bc0  ) ^ (brow&7)) & 7))*16);
    const uint32_t bOff1 = (uint32_t)(brow*256 + (((bc0+1) & 8) | (((bc0+1) ^ (brow&7)) & 7))*16);

    float acc[4][4][4];
#pragma unroll
    for (int i=0;i<4;i++)
#pragma unroll
        for (int j=0;j<4;j++)
#pragma unroll
            for (int q=0;q<4;q++) acc[i][j][q] = 0.f;

    const int NC = K >> 5;
    auto load_stage = [&](int c, int st) {
        const uint32_t s0 = sb + st*STG_BYTES;
        const int k0 = c << 5;
        const __nv_bfloat16* ga = Ah + (size_t)(m0 + arow)*K + k0 + ac0*8;
        cpa16(s0 + aOff0, ga);
        cpa16(s0 + aOff1, ga + 8);
        const __nv_bfloat16* gla = Al + (size_t)(m0 + arow)*K + k0 + ac0*8;
        cpa16(s0 + 8192 + aOff0, gla);
        cpa16(s0 + 8192 + aOff1, gla + 8);
        const __nv_bfloat16* gb = Bh + (size_t)(k0 + brow)*N + n0 + bc0*8;
        cpa16(s0 + 16384 + bOff0, gb);
        cpa16(s0 + 16384 + bOff1, gb + 8);
        const __nv_bfloat16* glb = Bl + (size_t)(k0 + brow)*N + n0 + bc0*8;
        cpa16(s0 + 24576 + bOff0, glb);
        cpa16(s0 + 24576 + bOff1, glb + 8);
        cpa_commit();
    };

    load_stage(0, 0);
    const int mat = lane >> 3, j8 = lane & 7;

    for (int c = 0; c < NC; c++) {
        if (c + 1 < NC) load_stage(c+1, (c+1)&1);
        if (c + 1 < NC) { cpa_wait<1>(); } else { cpa_wait<0>(); }
        __syncthreads();

        const uint32_t s0 = sb + (c&1)*STG_BYTES;
        const uint32_t sAh = s0, sAl = s0 + 8192, sBh = s0 + 16384, sBl = s0 + 24576;

#pragma unroll
        for (int k16 = 0; k16 < 2; k16++) {
            uint32_t fah[4][4], fal[4][4];
#pragma unroll
            for (int mi=0;mi<4;mi++) {
                int row = wm*64 + mi*16 + (mat&1)*8 + j8;
                int cc  = (k16*2 + (mat>>1)) ^ ((row>>1)&3);
                uint32_t off = (uint32_t)(row*64 + cc*16);
                ldsm_x4(fah[mi], sAh + off);
                ldsm_x4(fal[mi], sAl + off);
            }
            uint32_t fbh[4][2], fbl[4][2];
#pragma unroll
            for (int bi=0;bi<2;bi++) {
                int row = k16*16 + (mat&1)*8 + j8;
                int cn  = wn*4 + bi*2 + (mat>>1);
                int cc  = (cn & 8) | ((cn ^ (row&7)) & 7);
                uint32_t off = (uint32_t)(row*256 + cc*16);
                uint32_t r4[4];
                ldsm_x4t(r4, sBh + off);
                fbh[2*bi][0]=r4[0]; fbh[2*bi][1]=r4[1]; fbh[2*bi+1][0]=r4[2]; fbh[2*bi+1][1]=r4[3];
                ldsm_x4t(r4, sBl + off);
                fbl[2*bi][0]=r4[0]; fbl[2*bi][1]=r4[1]; fbl[2*bi+1][0]=r4[2]; fbl[2*bi+1][1]=r4[3];
            }
#pragma unroll
            for (int mi=0;mi<4;mi++)
#pragma unroll
                for (int ni=0;ni<4;ni++) {
                    mma16816(acc[mi][ni], fah[mi], fbh[ni]);
                    mma16816(acc[mi][ni], fal[mi], fbh[ni]);
                    mma16816(acc[mi][ni], fah[mi], fbl[ni]);
                }
        }
        __syncthreads();
    }

    const int lr = lane >> 2, lc = (lane & 3) * 2;
#pragma unroll
    for (int mi=0;mi<4;mi++) {
#pragma unroll
        for (int hh=0;hh<2;hh++) {
            const int m = m0 + wm*64 + mi*16 + hh*8 + lr;
#pragma unroll
            for (int ni=0;ni<4;ni++) {
                const int n = n0 + wn*32 + ni*8 + lc;
                float bn0 = (z==2) ? (b2a[n]   + b2b[n])   : (z==1 ? b1[n]   : b0[n]);
                float bn1 = (z==2) ? (b2a[n+1] + b2b[n+1]) : (z==1 ? b1[n+1] : b0[n+1]);
                float v0 = acc[mi][ni][2*hh]   + bn0;
                float v1 = acc[mi][ni][2*hh+1] + bn1;
                int b_ = m >> 12, t_ = m & 4095;
                *reinterpret_cast<float2*>(&Cf[(size_t)t_*(BB*UU) + b_*UU + n]) =
                    make_float2(v0, v1);
            }
        }
    }
}

// ---------------- persistent tensor-core CfC scan (96 CTAs, 8u, 3 gates) ----
// M rows 0..23 valid: gate = r>>3 (0:ff1, 1:ff2, 2:ta+tb), ul = r&7; rows 24..31 zero.
__global__ void __launch_bounds__(384, 1) scan_k(
    const float* __restrict__ Wh1, const float* __restrict__ Wh2,
    const float* __restrict__ Wha, const float* __restrict__ Whb,
    const float* __restrict__ x1,  const float* __restrict__ x2,
    const float* __restrict__ xab, int layer)
{
    __shared__ __align__(16) __nv_bfloat16 sH[UU*8];   // h hi, [k][8]
    __shared__ __align__(16) __nv_bfloat16 sL[UU*8];   // h lo
    __shared__ float part[2][6][16][8];                // [mt][ks][m][b]

    const int tid  = threadIdx.x;
    const int wid  = tid >> 5, lane = tid & 31;
    const int mt   = wid & 1, ks = wid >> 1;
    const int ublk = blockIdx.x * 8;
    const int g    = lane >> 2, tg = lane & 3;
    const uint32_t sHb = smem_u32(sH), sLb = smem_u32(sL);
    const unsigned tbase = (unsigned)layer * TT * NSCAN;

    // ---- load W fragments into registers (once); rows>=24 are zero ----
    const int r0 = mt*16 + g, r1 = r0 + 8;
    auto wv = [&](int r, int k) -> float {
        if (r >= 24) return 0.f;
        int gate = r >> 3, u = ublk + (r & 7);
        if (gate == 0) return Wh1[(size_t)k*UU + u];
        if (gate == 1) return Wh2[(size_t)k*UU + u];
        return Wha[(size_t)k*UU + u] + Whb[(size_t)k*UU + u];
    };
    uint32_t Afh[8][4], Afl[8][4];
#pragma unroll
    for (int j=0;j<8;j++) {
        const int kb = ks*128 + j*16 + tg*2;
        float w00 = wv(r0, kb),   w01 = wv(r0, kb+1);
        float w10 = wv(r1, kb),   w11 = wv(r1, kb+1);
        float w20 = wv(r0, kb+8), w21 = wv(r0, kb+9);
        float w30 = wv(r1, kb+8), w31 = wv(r1, kb+9);
        Afh[j][0] = pkbf(w00, w01); Afl[j][0] = pkbf(bflo(w00), bflo(w01));
        Afh[j][1] = pkbf(w10, w11); Afl[j][1] = pkbf(bflo(w10), bflo(w11));
        Afh[j][2] = pkbf(w20, w21); Afl[j][2] = pkbf(bflo(w20), bflo(w21));
        Afh[j][3] = pkbf(w30, w31); Afl[j][3] = pkbf(bflo(w30), bflo(w31));
    }

    // finalize mapping (tid < 64): (u-local 0..7, batch 0..7)
    const int ful = tid >> 3, fB = tid & 7;
    const int fug = ublk + ful;

    // prefetch xpre for t=0
    float p1=0.f, p2=0.f, pab=0.f;
    if (tid < 64) {
        int xi = fB*UU + fug;
        p1 = x1[xi]; p2 = x2[xi]; pab = xab[xi];
    }

    const int rr0 = tid*2;

    for (int t = 0; t < TT; t++) {
        // ---- stage h into smem (hi/lo split) ----
        if (t == 0) {
            uint4 z = make_uint4(0,0,0,0);
            *reinterpret_cast<uint4*>(&sH[rr0*8])     = z;
            *reinterpret_cast<uint4*>(&sH[(rr0+1)*8]) = z;
            *reinterpret_cast<uint4*>(&sL[rr0*8])     = z;
            *reinterpret_cast<uint4*>(&sL[(rr0+1)*8]) = z;
        } else {
            const uint4* gp = reinterpret_cast<const uint4*>(&g_hu[t & 1][0]);
#pragma unroll
            for (int rr=0; rr<2; rr++) {
                uint4 q0 = __ldcg(gp + (rr0+rr)*2);
                uint4 q1 = __ldcg(gp + (rr0+rr)*2 + 1);
                uint4 hi, lo;
                hi.x = __byte_perm(q0.x, q0.y, 0x5410); hi.y = __byte_perm(q0.z, q0.w, 0x5410);
                hi.z = __byte_perm(q1.x, q1.y, 0x5410); hi.w = __byte_perm(q1.z, q1.w, 0x5410);
                lo.x = __byte_perm(q0.x, q0.y, 0x7632); lo.y = __byte_perm(q0.z, q0.w, 0x7632);
                lo.z = __byte_perm(q1.x, q1.y, 0x7632); lo.w = __byte_perm(q1.z, q1.w, 0x7632);
                *reinterpret_cast<uint4*>(&sH[(rr0+rr)*8]) = hi;
                *reinterpret_cast<uint4*>(&sL[(rr0+rr)*8]) = lo;
            }
        }
        __syncthreads();

        // ---- MMA phase: 3 independent accumulator chains ----
        float ac0[4] = {0.f,0.f,0.f,0.f};
        float ac1[4] = {0.f,0.f,0.f,0.f};
        float ac2[4] = {0.f,0.f,0.f,0.f};
        const int krow = ks*128 + (lane & 15);
#pragma unroll
        for (int j=0;j<8;j++) {
            uint32_t bh[2], bl[2];
            uint32_t off = (uint32_t)((krow + j*16) * 16);
            ldsm_x2t(bh, sHb + off);
            ldsm_x2t(bl, sLb + off);
            mma16816(ac0, Afh[j], bh);
            mma16816(ac1, Afl[j], bh);
            mma16816(ac2, Afh[j], bl);
        }
        float acc[4];
#pragma unroll
        for (int q=0;q<4;q++) acc[q] = (ac0[q] + ac1[q]) + ac2[q];
        *reinterpret_cast<float2*>(&part[mt][ks][g][tg*2])   = make_float2(acc[0], acc[1]);
        *reinterpret_cast<float2*>(&part[mt][ks][g+8][tg*2]) = make_float2(acc[2], acc[3]);
        __syncthreads();

        // ---- finalize (64 threads) + release + hidden work + poll ----
        if (tid < 64) {
            float s0=0.f, s1=0.f, s2=0.f;
#pragma unroll
            for (int k6=0;k6<6;k6++) {
                s0 += part[0][k6][ful][fB];       // gate ff1 (rows 0..7)
                s1 += part[0][k6][8+ful][fB];     // gate ff2 (rows 8..15)
                s2 += part[1][k6][ful][fB];       // gate ta+tb (rows 16..23)
            }
            float f1 = ftanh(s0 + p1), f2 = ftanh(s1 + p2);
            float ti = fsigm(s2 + pab);
            float hn = f1 + ti*(f2 - f1);
            float hl = bflo(hn);
            unsigned pk = ((uint32_t)__bfloat16_as_ushort(__float2bfloat16(hl)) << 16)
                        | __bfloat16_as_ushort(__float2bfloat16(hn));
            unsigned* dst = &g_hu[1-(t&1)][fug*8 + fB];
            asm volatile("st.global.cg.u32 [%0], %1;" :: "l"(dst), "r"(pk) : "memory");
            asm volatile("bar.sync 1, 64;" ::: "memory");   // all 64 h stores issued
            if (tid == 0) bar_red_release(&g_bar);
            // hidden under other CTAs' arrival:
            if (fug < DD) g_cfc[((size_t)fB*TT + t)*DD + fug] = hn;
            if (t+1 < TT) {
                int xi = (t+1)*(BB*UU) + fB*UU + fug;
                p1 = x1[xi]; p2 = x2[xi]; pab = xab[xi];
            }
            if (tid == 0 && t+1 < TT) {
                unsigned target = tbase + (unsigned)(t+1)*NSCAN;
                while (ld_acquire(&g_bar) < target) {}
            }
        }
        __syncthreads();
    }
}

// ---------------- LIF gate + residual add -----------------------------------
__global__ void lif_k(const float* __restrict__ thr_p,
                      const float* __restrict__ leak_p,
                      const float* __restrict__ steep_p) {
    int e = blockIdx.x*256 + threadIdx.x;
    int d = e & 511;
    float thr  = fabsf(thr_p[d]) * 0.1f;
    float leak = 1.f/(1.f + expf(-leak_p[d]));
    float sv = steep_p[d];
    float steep = (sv > 20.f) ? sv : log1pf(expf(sv));
    float c = g_cfc[e];
    float fire = 1.f/(1.f + expf(-steep*(fabsf(c) - thr)));
    float gate = fire + leak*(1.f - fire);
    g_x[e] += c*gate;
}

// ---------------- loss -------------------------------------------------------
__global__ void loss_k(const int* __restrict__ tgt, const float* __restrict__ logits) {
    int row  = blockIdx.x*8 + (threadIdx.x >> 5);
    int lane = threadIdx.x & 31;
    const float* lr = logits + (size_t)row*VV;
    float v[8]; float mx = -3.4e38f;
#pragma unroll
    for (int j=0;j<8;j++) { v[j] = lr[lane + 32*j]; mx = fmaxf(mx, v[j]); }
#pragma unroll
    for (int off=16; off; off>>=1) mx = fmaxf(mx, __shfl_xor_sync(0xffffffffu, mx, off));
    float se = 0.f;
#pragma unroll
    for (int j=0;j<8;j++) se += expf(v[j]-mx);
#pragma unroll
    for (int off=16; off; off>>=1) se += __shfl_xor_sync(0xffffffffu, se, off);
    if (lane == 0) {
        int tv = tgt[row];
        if (tv >= 0) {
            float nll = mx + logf(se) - lr[tv];
            atomicAdd(&g_loss[0], nll);
            atomicAdd(&g_loss[1], 1.f);
        }
    }
}

__global__ void fin_k(float* __restrict__ out, int out_size) {
    if (out_size > MM*VV) out[MM*VV] = g_loss[0]/g_loss[1];
}

// ---------------- driver ------------------------------------------------------
extern "C" void kernel_launch(void* const* d_in, const int* in_sizes, int n_in,
                              void* d_out, int out_size) {
    (void)in_sizes; (void)n_in;
    const int*   idx      = (const int*)  d_in[0];
    const int*   targets  = (const int*)  d_in[1];
    const float* wte      = (const float*)d_in[2];
    const float* ln1_s    = (const float*)d_in[3];
    const float* ln1_b    = (const float*)d_in[4];
    const float* Wff1     = (const float*)d_in[5];
    const float* bff1     = (const float*)d_in[6];
    const float* Wff2     = (const float*)d_in[7];
    const float* bff2     = (const float*)d_in[8];
    const float* Wta      = (const float*)d_in[9];
    const float* bta      = (const float*)d_in[10];
    const float* Wtb      = (const float*)d_in[11];
    const float* btb      = (const float*)d_in[12];
    const float* lif_thr  = (const float*)d_in[13];
    const float* lif_leak = (const float*)d_in[14];
    const float* lif_stp  = (const float*)d_in[15];
    const float* ln2_s    = (const float*)d_in[16];
    const float* ln2_b    = (const float*)d_in[17];
    const float* mW1      = (const float*)d_in[18];
    const float* mb1      = (const float*)d_in[19];
    const float* mW2      = (const float*)d_in[20];
    const float* mb2      = (const float*)d_in[21];
    const float* lnf_s    = (const float*)d_in[22];
    const float* lnf_b    = (const float*)d_in[23];
    float* out = (float*)d_out;

    cudaFuncSetAttribute(mm_gemm<0,true>,  cudaFuncAttributeMaxDynamicSharedMemorySize, GSMEM);
    cudaFuncSetAttribute(mm_gemm<2,false>, cudaFuncAttributeMaxDynamicSharedMemorySize, GSMEM);
    cudaFuncSetAttribute(mm_gemm<3,false>, cudaFuncAttributeMaxDynamicSharedMemorySize, GSMEM);
    cudaFuncSetAttribute(mm_gemm_p,        cudaFuncAttributeMaxDynamicSharedMemorySize, GSMEM);

    float *xp, *xpre;
    __nv_bfloat16 *ah1, *al1, *ah2, *al2, *wh, *wl, *wteh, *wtel;
    cudaGetSymbolAddress((void**)&xp,   g_x);
    cudaGetSymbolAddress((void**)&xpre, g_xpre);
    cudaGetSymbolAddress((void**)&ah1,  g_ah1);
    cudaGetSymbolAddress((void**)&al1,  g_al1);
    cudaGetSymbolAddress((void**)&ah2,  g_ah2);
    cudaGetSymbolAddress((void**)&al2,  g_al2);
    cudaGetSymbolAddress((void**)&wh,   g_wh);
    cudaGetSymbolAddress((void**)&wl,   g_wl);
    cudaGetSymbolAddress((void**)&wteh, g_wteh);
    cudaGetSymbolAddress((void**)&wtel, g_wtel);

    const size_t WSTRIDE = (size_t)(DD+UU)*UU;
    const size_t XG = (size_t)TT*BB*UU;

    for (int l = 0; l < LL; l++) {
        if (l == 0) {
            embln_k<<<MM/2, 256>>>(idx, wte, ln1_s, ln1_b, ah1, al1);    // launch 1
        } else {
            ln_bf_k<<<MM,128>>>(xp, ln1_s + l*DD, ln1_b + l*DD, ah1, al1);
        }
        cvt3_k<<<3*DD*UU/256, 256>>>(                                    // launch 2
            Wff1 + (size_t)l*WSTRIDE, Wff2 + (size_t)l*WSTRIDE,
            Wta  + (size_t)l*WSTRIDE, Wtb  + (size_t)l*WSTRIDE, wh, wl);
        mm_gemm_p<<<dim3(UU/128, MM/128, 3), 256, GSMEM>>>(              // launch 3
            ah1, al1, wh, wl,
            bff1 + l*UU, bff2 + l*UU, bta + l*UU, btb + l*UU, xpre);

        scan_k<<<NSCAN, 384>>>(                                          // launch 4 (ncu)
            Wff1 + (size_t)l*WSTRIDE + (size_t)DD*UU,
            Wff2 + (size_t)l*WSTRIDE + (size_t)DD*UU,
            Wta  + (size_t)l*WSTRIDE + (size_t)DD*UU,
            Wtb  + (size_t)l*WSTRIDE + (size_t)DD*UU,
            xpre, xpre + XG, xpre + 2*XG, l);

        lif_k<<<MM*DD/256, 256>>>(lif_thr + l*DD, lif_leak + l*DD, lif_stp + l*DD);

        ln_bf_k<<<MM,128>>>(xp, ln2_s + l*DD, ln2_b + l*DD, ah1, al1);
        cvt_e_k<<<DD*DFFC/256, 256>>>(mW1 + (size_t)l*DD*DFFC, wh, wl);
        mm_gemm<2,false><<<dim3(DFFC/128, MM/128), 256, GSMEM>>>(
            ah1, al1, wh, wl, mb1 + l*DFFC, nullptr,
            nullptr, ah2, al2, DFFC, DD);
        cvt_e_k<<<DFFC*DD/256, 256>>>(mW2 + (size_t)l*DFFC*DD, wh, wl);
        mm_gemm<3,false><<<dim3(DD/128, MM/128), 256, GSMEM>>>(
            ah2, al2, wh, wl, mb2 + l*DD, xp,
            xp, nullptr, nullptr, DD, DFFC);
    }

    ln_bf_k<<<MM,128>>>(xp, lnf_s, lnf_b, ah1, al1);
    cvt_e_k<<<VV*DD/256, 256>>>(wte, wteh, wtel);
    mm_gemm<0,true><<<dim3(VV/128, MM/128), 256, GSMEM>>>(
        ah1, al1, wteh, wtel, nullptr, nullptr,
        out, nullptr, nullptr, VV, DD);
    loss_k<<<MM/8, 256>>>(targets, out);
    fin_k<<<1,1>>>(out, out_size);
}

// round 14
// speedup vs baseline: 1.0835x; 1.0235x over previous
#include <cuda_runtime.h>
#include <cuda_bf16.h>
#include <math.h>
#include <cstdint>

#define BB 8
#define TT 4096
#define DD 512
#define UU 768
#define LL 4
#define VV 256
#define DFFC 2048
#define MM (BB*TT)          // 32768 rows
#define NSCAN 96            // persistent scan CTAs (8 u-cols each)

typedef unsigned long long ull;

// ---------------- PTX helpers ----------------------------------------------
__device__ __forceinline__ void bar_red_release(unsigned* p) {
    asm volatile("red.release.gpu.add.u32 [%0], 1;" :: "l"(p) : "memory");
}
__device__ __forceinline__ unsigned ld_acquire(const unsigned* p) {
    unsigned v;
    asm volatile("ld.acquire.gpu.u32 %0, [%1];" : "=r"(v) : "l"(p) : "memory");
    return v;
}
__device__ __forceinline__ uint32_t smem_u32(const void* p) {
    uint32_t a;
    asm("{ .reg .u64 t; cvta.to.shared.u64 t, %1; cvt.u32.u64 %0, t; }" : "=r"(a) : "l"(p));
    return a;
}
__device__ __forceinline__ void cpa16(uint32_t s, const void* g) {
    asm volatile("cp.async.cg.shared.global [%0], [%1], 16;" :: "r"(s), "l"(g));
}
__device__ __forceinline__ void cpa_commit() {
    asm volatile("cp.async.commit_group;" ::: "memory");
}
template<int N>
__device__ __forceinline__ void cpa_wait() {
    asm volatile("cp.async.wait_group %0;" :: "n"(N) : "memory");
}
__device__ __forceinline__ void ldsm_x4(uint32_t* r, uint32_t a) {
    asm volatile("ldmatrix.sync.aligned.m8n8.x4.shared.b16 {%0,%1,%2,%3}, [%4];"
        : "=r"(r[0]), "=r"(r[1]), "=r"(r[2]), "=r"(r[3]) : "r"(a));
}
__device__ __forceinline__ void ldsm_x4t(uint32_t* r, uint32_t a) {
    asm volatile("ldmatrix.sync.aligned.m8n8.x4.trans.shared.b16 {%0,%1,%2,%3}, [%4];"
        : "=r"(r[0]), "=r"(r[1]), "=r"(r[2]), "=r"(r[3]) : "r"(a));
}
__device__ __forceinline__ void ldsm_x2t(uint32_t* r, uint32_t a) {
    asm volatile("ldmatrix.sync.aligned.m8n8.x2.trans.shared.b16 {%0,%1}, [%2];"
        : "=r"(r[0]), "=r"(r[1]) : "r"(a));
}
__device__ __forceinline__ void mma16816(float* d, const uint32_t* a, const uint32_t* b) {
    asm volatile("mma.sync.aligned.m16n8k16.row.col.f32.bf16.bf16.f32 "
        "{%0,%1,%2,%3}, {%4,%5,%6,%7}, {%8,%9}, {%0,%1,%2,%3};"
        : "+f"(d[0]), "+f"(d[1]), "+f"(d[2]), "+f"(d[3])
        : "r"(a[0]), "r"(a[1]), "r"(a[2]), "r"(a[3]), "r"(b[0]), "r"(b[1]));
}
__device__ __forceinline__ uint32_t pkbf(float v0, float v1) {
    __nv_bfloat16 h0 = __float2bfloat16(v0), h1 = __float2bfloat16(v1);
    return ((uint32_t)__bfloat16_as_ushort(h1) << 16) | __bfloat16_as_ushort(h0);
}
__device__ __forceinline__ float bflo(float v) {
    return v - __bfloat162float(__float2bfloat16(v));
}
// fast transcendentals (MUFU ex2/rcp based; rel err ~1e-6)
__device__ __forceinline__ float ftanh(float x) {
    float e = __expf(2.f*x);
    return __fdividef(e - 1.f, e + 1.f);
}
__device__ __forceinline__ float fsigm(float x) {
    return __fdividef(1.f, 1.f + __expf(-x));
}

// ---------------- scratch ---------------------------------------------------
__device__ float g_x[MM*DD];
__device__ float g_xpre[3][TT*BB*UU];     // x1, x2, xab (fused a+b)
__device__ float g_cfc[MM*DD];
__device__ unsigned int g_hu[2][UU*BB];   // h as packed (bf16 hi | bf16 lo<<16), [k][b]
__device__ float g_loss[2];
__device__ unsigned int g_bar;            // monotonic across layers within a launch
__device__ __nv_bfloat16 g_ah1[MM*DD],  g_al1[MM*DD];
__device__ __nv_bfloat16 g_ah2[(size_t)MM*DFFC], g_al2[(size_t)MM*DFFC];
__device__ __nv_bfloat16 g_wh[4*DD*UU], g_wl[4*DD*UU];   // ≥ max(3*DD*UU, DFFC*DD)
__device__ __nv_bfloat16 g_wteh[VV*DD], g_wtel[VV*DD];

// ---------------- fused embed + LN1(layer0) + state reset --------------------
__global__ void embln_k(const int* __restrict__ idx, const float* __restrict__ wte,
                        const float* __restrict__ s, const float* __restrict__ b,
                        __nv_bfloat16* __restrict__ oh, __nv_bfloat16* __restrict__ ol) {
    __shared__ float red[2][8];
    if (blockIdx.x == 0 && threadIdx.x == 0) {
        g_bar = 0u; g_loss[0] = 0.f; g_loss[1] = 0.f;
    }
    const int half = threadIdx.x >> 7;
    const int wg   = threadIdx.x & 127;
    const int row  = blockIdx.x*2 + half;
    const int tok  = idx[row];
    float v[4]; float sum = 0.f, sq = 0.f;
#pragma unroll
    for (int j=0;j<4;j++) {
        v[j] = wte[(size_t)tok*DD + wg + j*128];
        g_x[(size_t)row*DD + wg + j*128] = v[j];
        sum += v[j]; sq += v[j]*v[j];
    }
#pragma unroll
    for (int off=16; off; off>>=1) {
        sum += __shfl_xor_sync(0xffffffffu, sum, off);
        sq  += __shfl_xor_sync(0xffffffffu, sq,  off);
    }
    int w = wg >> 5, lane = wg & 31;
    if (lane == 0) { red[half][w] = sum; }
    __syncthreads();
    if (lane == 1 && w == 0) {
        red[half][0] = red[half][0]+red[half][1]+red[half][2]+red[half][3];
    }
    __syncthreads();
    if (lane == 0) { red[half][4+w] = sq; }
    __syncthreads();
    if (lane == 1 && w == 0) {
        red[half][4] = red[half][4]+red[half][5]+red[half][6]+red[half][7];
    }
    __syncthreads();
    float mean = red[half][0]*(1.f/512.f);
    float var  = red[half][4]*(1.f/512.f) - mean*mean;
    float r = rsqrtf(var + 1e-5f);
#pragma unroll
    for (int j=0;j<4;j++) {
        int d = wg + j*128;
        float t = (v[j]-mean)*r*s[d] + b[d];
        __nv_bfloat16 h = __float2bfloat16(t);
        __nv_bfloat16 l = __float2bfloat16(t - __bfloat162float(h));
        oh[(size_t)row*DD + d] = h;
        ol[(size_t)row*DD + d] = l;
    }
}

// ---------------- layernorm -> bf16 hi/lo -----------------------------------
__global__ void ln_bf_k(const float* __restrict__ in, const float* __restrict__ s,
                        const float* __restrict__ b,
                        __nv_bfloat16* __restrict__ oh, __nv_bfloat16* __restrict__ ol) {
    __shared__ float red[8];
    int row = blockIdx.x;
    const float* x = in + (size_t)row*DD;
    float v[4]; float sum = 0.f, sq = 0.f;
#pragma unroll
    for (int j=0;j<4;j++) { v[j] = x[threadIdx.x + j*128]; sum += v[j]; sq += v[j]*v[j]; }
#pragma unroll
    for (int off=16; off; off>>=1) {
        sum += __shfl_xor_sync(0xffffffffu, sum, off);
        sq  += __shfl_xor_sync(0xffffffffu, sq,  off);
    }
    int w = threadIdx.x >> 5, lane = threadIdx.x & 31;
    if (lane == 0) { red[w] = sum; red[4+w] = sq; }
    __syncthreads();
    if (threadIdx.x == 0) {
        red[0] = red[0]+red[1]+red[2]+red[3];
        red[4] = red[4]+red[5]+red[6]+red[7];
    }
    __syncthreads();
    float mean = red[0]*(1.f/512.f);
    float var  = red[4]*(1.f/512.f) - mean*mean;
    float r = rsqrtf(var + 1e-5f);
#pragma unroll
    for (int j=0;j<4;j++) {
        int d = threadIdx.x + j*128;
        float t = (v[j]-mean)*r*s[d] + b[d];
        __nv_bfloat16 h = __float2bfloat16(t);
        __nv_bfloat16 l = __float2bfloat16(t - __bfloat162float(h));
        oh[(size_t)row*DD + d] = h;
        ol[(size_t)row*DD + d] = l;
    }
}

// ---------------- elementwise f32 -> bf16 hi/lo ------------------------------
__global__ void cvt_e_k(const float* __restrict__ X,
                        __nv_bfloat16* __restrict__ oh, __nv_bfloat16* __restrict__ ol) {
    int e = blockIdx.x*256 + threadIdx.x;
    float x = X[e];
    __nv_bfloat16 h = __float2bfloat16(x);
    __nv_bfloat16 l = __float2bfloat16(x - __bfloat162float(h));
    oh[e] = h; ol[e] = l;
}

// ---------------- fused 3-gate weight convert (gate2 = Wta+Wtb) --------------
__global__ void cvt3_k(const float* __restrict__ W0, const float* __restrict__ W1,
                       const float* __restrict__ W2a, const float* __restrict__ W2b,
                       __nv_bfloat16* __restrict__ oh, __nv_bfloat16* __restrict__ ol) {
    int e = blockIdx.x*256 + threadIdx.x;          // over 3*DD*UU
    int gate = e / (DD*UU);
    int off  = e - gate*(DD*UU);
    float x = (gate==0) ? W0[off] : (gate==1) ? W1[off] : (W2a[off] + W2b[off]);
    __nv_bfloat16 h = __float2bfloat16(x);
    __nv_bfloat16 l = __float2bfloat16(x - __bfloat162float(h));
    oh[e] = h; ol[e] = l;
}

// ---------------- bf16x3 tensor-core GEMM (mma.sync) — R7, unchanged --------
#define STG_BYTES 32768
#define GSMEM (2*STG_BYTES)

template<int EPI, bool BTR>
__global__ void __launch_bounds__(256) mm_gemm(
    const __nv_bfloat16* __restrict__ Ah, const __nv_bfloat16* __restrict__ Al,
    const __nv_bfloat16* __restrict__ Bh, const __nv_bfloat16* __restrict__ Bl,
    const float* __restrict__ bias, const float* __restrict__ R,
    float* __restrict__ Cf, __nv_bfloat16* __restrict__ Ch, __nv_bfloat16* __restrict__ Cl,
    int N, int K)
{
    extern __shared__ char sm[];
    const uint32_t sb = smem_u32(sm);
    const int tid = threadIdx.x, wid = tid >> 5, lane = tid & 31;
    const int wm = wid & 1, wn = wid >> 1;
    const int m0 = blockIdx.y << 7, n0 = blockIdx.x << 7;

    const int arow = tid >> 1, ac0 = (tid & 1) * 2;
    const int as   = (arow >> 1) & 3;
    const uint32_t aOff0 = (uint32_t)(arow*64 + ((ac0   ^ as) & 3)*16);
    const uint32_t aOff1 = (uint32_t)(arow*64 + (((ac0+1)^ as) & 3)*16);
    const int brow = tid >> 3, bc0 = (tid & 7) * 2;
    const uint32_t bOff0 = (uint32_t)(brow*256 + (((bc0  ) & 8) | (((bc0  ) ^ (brow&7)) & 7))*16);
    const uint32_t bOff1 = (uint32_t)(brow*256 + (((bc0+1) & 8) | (((bc0+1) ^ (brow&7)) & 7))*16);

    float acc[4][4][4];
#pragma unroll
    for (int i=0;i<4;i++)
#pragma unroll
        for (int j=0;j<4;j++)
#pragma unroll
            for (int q=0;q<4;q++) acc[i][j][q] = 0.f;

    const int NC = K >> 5;

    auto load_stage = [&](int c, int st) {
        const uint32_t s0 = sb + st*STG_BYTES;
        const int k0 = c << 5;
        {
            const __nv_bfloat16* ga = Ah + (size_t)(m0 + arow)*K + k0 + ac0*8;
            cpa16(s0 + aOff0, ga);
            cpa16(s0 + aOff1, ga + 8);
            const __nv_bfloat16* gl = Al + (size_t)(m0 + arow)*K + k0 + ac0*8;
            cpa16(s0 + 8192 + aOff0, gl);
            cpa16(s0 + 8192 + aOff1, gl + 8);
        }
        if (!BTR) {
            const __nv_bfloat16* gb = Bh + (size_t)(k0 + brow)*N + n0 + bc0*8;
            cpa16(s0 + 16384 + bOff0, gb);
            cpa16(s0 + 16384 + bOff1, gb + 8);
            const __nv_bfloat16* gl = Bl + (size_t)(k0 + brow)*N + n0 + bc0*8;
            cpa16(s0 + 24576 + bOff0, gl);
            cpa16(s0 + 24576 + bOff1, gl + 8);
        } else {
            const __nv_bfloat16* gb = Bh + (size_t)(n0 + arow)*K + k0 + ac0*8;
            cpa16(s0 + 16384 + aOff0, gb);
            cpa16(s0 + 16384 + aOff1, gb + 8);
            const __nv_bfloat16* gl = Bl + (size_t)(n0 + arow)*K + k0 + ac0*8;
            cpa16(s0 + 24576 + aOff0, gl);
            cpa16(s0 + 24576 + aOff1, gl + 8);
        }
        cpa_commit();
    };

    load_stage(0, 0);
    const int mat = lane >> 3, j8 = lane & 7;

    for (int c = 0; c < NC; c++) {
        if (c + 1 < NC) load_stage(c+1, (c+1)&1);
        if (c + 1 < NC) { cpa_wait<1>(); } else { cpa_wait<0>(); }
        __syncthreads();

        const uint32_t s0 = sb + (c&1)*STG_BYTES;
        const uint32_t sAh = s0, sAl = s0 + 8192, sBh = s0 + 16384, sBl = s0 + 24576;

#pragma unroll
        for (int k16 = 0; k16 < 2; k16++) {
            uint32_t fah[4][4], fal[4][4];
#pragma unroll
            for (int mi=0;mi<4;mi++) {
                int row = wm*64 + mi*16 + (mat&1)*8 + j8;
                int cc  = (k16*2 + (mat>>1)) ^ ((row>>1)&3);
                uint32_t off = (uint32_t)(row*64 + cc*16);
                ldsm_x4(fah[mi], sAh + off);
                ldsm_x4(fal[mi], sAl + off);
            }
            uint32_t fbh[4][2], fbl[4][2];
            if (!BTR) {
#pragma unroll
                for (int bi=0;bi<2;bi++) {
                    int row = k16*16 + (mat&1)*8 + j8;
                    int cn  = wn*4 + bi*2 + (mat>>1);
                    int cc  = (cn & 8) | ((cn ^ (row&7)) & 7);
                    uint32_t off = (uint32_t)(row*256 + cc*16);
                    uint32_t r4[4];
                    ldsm_x4t(r4, sBh + off);
                    fbh[2*bi][0]=r4[0]; fbh[2*bi][1]=r4[1]; fbh[2*bi+1][0]=r4[2]; fbh[2*bi+1][1]=r4[3];
                    ldsm_x4t(r4, sBl + off);
                    fbl[2*bi][0]=r4[0]; fbl[2*bi][1]=r4[1]; fbl[2*bi+1][0]=r4[2]; fbl[2*bi+1][1]=r4[3];
                }
            } else {
#pragma unroll
                for (int bi=0;bi<2;bi++) {
                    int row = wn*32 + bi*16 + (mat>>1)*8 + j8;
                    int cc  = (k16*2 + (mat&1)) ^ ((row>>1)&3);
                    uint32_t off = (uint32_t)(row*64 + cc*16);
                    uint32_t r4[4];
                    ldsm_x4(r4, sBh + off);
                    fbh[2*bi][0]=r4[0]; fbh[2*bi][1]=r4[1]; fbh[2*bi+1][0]=r4[2]; fbh[2*bi+1][1]=r4[3];
                    ldsm_x4(r4, sBl + off);
                    fbl[2*bi][0]=r4[0]; fbl[2*bi][1]=r4[1]; fbl[2*bi+1][0]=r4[2]; fbl[2*bi+1][1]=r4[3];
                }
            }
#pragma unroll
            for (int mi=0;mi<4;mi++)
#pragma unroll
                for (int ni=0;ni<4;ni++) {
                    mma16816(acc[mi][ni], fah[mi], fbh[ni]);
                    mma16816(acc[mi][ni], fal[mi], fbh[ni]);
                    mma16816(acc[mi][ni], fah[mi], fbl[ni]);
                }
        }
        __syncthreads();
    }

    const int lr = lane >> 2, lc = (lane & 3) * 2;
#pragma unroll
    for (int mi=0;mi<4;mi++) {
#pragma unroll
        for (int hh=0;hh<2;hh++) {
            const int m = m0 + wm*64 + mi*16 + hh*8 + lr;
#pragma unroll
            for (int ni=0;ni<4;ni++) {
                const int n = n0 + wn*32 + ni*8 + lc;
                float v0 = acc[mi][ni][2*hh], v1 = acc[mi][ni][2*hh+1];
                if (EPI != 0) { v0 += bias[n]; v1 += bias[n+1]; }
                if (EPI == 2) {
                    v0 = 0.5f*v0*(1.f + erff(v0*0.70710678118654752f));
                    v1 = 0.5f*v1*(1.f + erff(v1*0.70710678118654752f));
                    __nv_bfloat16 h0 = __float2bfloat16(v0);
                    __nv_bfloat16 h1 = __float2bfloat16(v1);
                    __nv_bfloat16 l0 = __float2bfloat16(v0 - __bfloat162float(h0));
                    __nv_bfloat16 l1 = __float2bfloat16(v1 - __bfloat162float(h1));
                    *reinterpret_cast<uint32_t*>(&Ch[(size_t)m*N + n]) =
                        ((uint32_t)__bfloat16_as_ushort(h1) << 16) | __bfloat16_as_ushort(h0);
                    *reinterpret_cast<uint32_t*>(&Cl[(size_t)m*N + n]) =
                        ((uint32_t)__bfloat16_as_ushort(l1) << 16) | __bfloat16_as_ushort(l0);
                } else if (EPI == 3) {
                    float2 r = *reinterpret_cast<const float2*>(&R[(size_t)m*N + n]);
                    *reinterpret_cast<float2*>(&Cf[(size_t)m*N + n]) =
                        make_float2(v0 + r.x, v1 + r.y);
                } else {
                    *reinterpret_cast<float2*>(&Cf[(size_t)m*N + n]) = make_float2(v0, v1);
                }
            }
        }
    }
}

// ---------------- fused projection GEMM (3 gates via blockIdx.z) -------------
__global__ void __launch_bounds__(256) mm_gemm_p(
    const __nv_bfloat16* __restrict__ Ah, const __nv_bfloat16* __restrict__ Al,
    const __nv_bfloat16* __restrict__ WhB, const __nv_bfloat16* __restrict__ WlB,
    const float* __restrict__ b0, const float* __restrict__ b1,
    const float* __restrict__ b2a, const float* __restrict__ b2b,
    float* __restrict__ xpre)
{
    extern __shared__ char sm[];
    const uint32_t sb = smem_u32(sm);
    const int tid = threadIdx.x, wid = tid >> 5, lane = tid & 31;
    const int wm = wid & 1, wn = wid >> 1;
    const int m0 = blockIdx.y << 7, n0 = blockIdx.x << 7;
    const int z  = blockIdx.z;
    const int N = UU, K = DD;
    const __nv_bfloat16* Bh = WhB + (size_t)z*DD*UU;
    const __nv_bfloat16* Bl = WlB + (size_t)z*DD*UU;
    float* Cf = xpre + (size_t)z*((size_t)TT*BB*UU);

    const int arow = tid >> 1, ac0 = (tid & 1) * 2;
    const int as   = (arow >> 1) & 3;
    const uint32_t aOff0 = (uint32_t)(arow*64 + ((ac0   ^ as) & 3)*16);
    const uint32_t aOff1 = (uint32_t)(arow*64 + (((ac0+1)^ as) & 3)*16);
    const int brow = tid >> 3, bc0 = (tid & 7) * 2;
    const uint32_t bOff0 = (uint32_t)(brow*256 + (((bc0  ) & 8) | (((bc0  ) ^ (brow&7)) & 7))*16);
    const uint32_t bOff1 = (uint32_t)(brow*256 + (((bc0+1) & 8) | (((bc0+1) ^ (brow&7)) & 7))*16);

    float acc[4][4][4];
#pragma unroll
    for (int i=0;i<4;i++)
#pragma unroll
        for (int j=0;j<4;j++)
#pragma unroll
            for (int q=0;q<4;q++) acc[i][j][q] = 0.f;

    const int NC = K >> 5;
    auto load_stage = [&](int c, int st) {
        const uint32_t s0 = sb + st*STG_BYTES;
        const int k0 = c << 5;
        const __nv_bfloat16* ga = Ah + (size_t)(m0 + arow)*K + k0 + ac0*8;
        cpa16(s0 + aOff0, ga);
        cpa16(s0 + aOff1, ga + 8);
        const __nv_bfloat16* gla = Al + (size_t)(m0 + arow)*K + k0 + ac0*8;
        cpa16(s0 + 8192 + aOff0, gla);
        cpa16(s0 + 8192 + aOff1, gla + 8);
        const __nv_bfloat16* gb = Bh + (size_t)(k0 + brow)*N + n0 + bc0*8;
        cpa16(s0 + 16384 + bOff0, gb);
        cpa16(s0 + 16384 + bOff1, gb + 8);
        const __nv_bfloat16* glb = Bl + (size_t)(k0 + brow)*N + n0 + bc0*8;
        cpa16(s0 + 24576 + bOff0, glb);
        cpa16(s0 + 24576 + bOff1, glb + 8);
        cpa_commit();
    };

    load_stage(0, 0);
    const int mat = lane >> 3, j8 = lane & 7;

    for (int c = 0; c < NC; c++) {
        if (c + 1 < NC) load_stage(c+1, (c+1)&1);
        if (c + 1 < NC) { cpa_wait<1>(); } else { cpa_wait<0>(); }
        __syncthreads();

        const uint32_t s0 = sb + (c&1)*STG_BYTES;
        const uint32_t sAh = s0, sAl = s0 + 8192, sBh = s0 + 16384, sBl = s0 + 24576;

#pragma unroll
        for (int k16 = 0; k16 < 2; k16++) {
            uint32_t fah[4][4], fal[4][4];
#pragma unroll
            for (int mi=0;mi<4;mi++) {
                int row = wm*64 + mi*16 + (mat&1)*8 + j8;
                int cc  = (k16*2 + (mat>>1)) ^ ((row>>1)&3);
                uint32_t off = (uint32_t)(row*64 + cc*16);
                ldsm_x4(fah[mi], sAh + off);
                ldsm_x4(fal[mi], sAl + off);
            }
            uint32_t fbh[4][2], fbl[4][2];
#pragma unroll
            for (int bi=0;bi<2;bi++) {
                int row = k16*16 + (mat&1)*8 + j8;
                int cn  = wn*4 + bi*2 + (mat>>1);
                int cc  = (cn & 8) | ((cn ^ (row&7)) & 7);
                uint32_t off = (uint32_t)(row*256 + cc*16);
                uint32_t r4[4];
                ldsm_x4t(r4, sBh + off);
                fbh[2*bi][0]=r4[0]; fbh[2*bi][1]=r4[1]; fbh[2*bi+1][0]=r4[2]; fbh[2*bi+1][1]=r4[3];
                ldsm_x4t(r4, sBl + off);
                fbl[2*bi][0]=r4[0]; fbl[2*bi][1]=r4[1]; fbl[2*bi+1][0]=r4[2]; fbl[2*bi+1][1]=r4[3];
            }
#pragma unroll
            for (int mi=0;mi<4;mi++)
#pragma unroll
                for (int ni=0;ni<4;ni++) {
                    mma16816(acc[mi][ni], fah[mi], fbh[ni]);
                    mma16816(acc[mi][ni], fal[mi], fbh[ni]);
                    mma16816(acc[mi][ni], fah[mi], fbl[ni]);
                }
        }
        __syncthreads();
    }

    const int lr = lane >> 2, lc = (lane & 3) * 2;
#pragma unroll
    for (int mi=0;mi<4;mi++) {
#pragma unroll
        for (int hh=0;hh<2;hh++) {
            const int m = m0 + wm*64 + mi*16 + hh*8 + lr;
#pragma unroll
            for (int ni=0;ni<4;ni++) {
                const int n = n0 + wn*32 + ni*8 + lc;
                float bn0 = (z==2) ? (b2a[n]   + b2b[n])   : (z==1 ? b1[n]   : b0[n]);
                float bn1 = (z==2) ? (b2a[n+1] + b2b[n+1]) : (z==1 ? b1[n+1] : b0[n+1]);
                float v0 = acc[mi][ni][2*hh]   + bn0;
                float v1 = acc[mi][ni][2*hh+1] + bn1;
                int b_ = m >> 12, t_ = m & 4095;
                *reinterpret_cast<float2*>(&Cf[(size_t)t_*(BB*UU) + b_*UU + n]) =
                    make_float2(v0, v1);
            }
        }
    }
}

// ---------------- persistent tensor-core CfC scan (96 CTAs, 8u, 3 gates) ----
// R14: xpre prefetch by dedicated loader group (tid 128..191) via double-
// buffered smem, removing DRAM-load jitter from the finalize critical chain.
__global__ void __launch_bounds__(384, 1) scan_k(
    const float* __restrict__ Wh1, const float* __restrict__ Wh2,
    const float* __restrict__ Wha, const float* __restrict__ Whb,
    const float* __restrict__ x1,  const float* __restrict__ x2,
    const float* __restrict__ xab, int layer)
{
    __shared__ __align__(16) __nv_bfloat16 sH[UU*8];   // h hi, [k][8]
    __shared__ __align__(16) __nv_bfloat16 sL[UU*8];   // h lo
    __shared__ float part[2][6][16][8];                // [mt][ks][m][b]
    __shared__ float sXP[2][3][64];                    // double-buffered xpre stage

    const int tid  = threadIdx.x;
    const int wid  = tid >> 5, lane = tid & 31;
    const int mt   = wid & 1, ks = wid >> 1;
    const int ublk = blockIdx.x * 8;
    const int g    = lane >> 2, tg = lane & 3;
    const uint32_t sHb = smem_u32(sH), sLb = smem_u32(sL);
    const unsigned tbase = (unsigned)layer * TT * NSCAN;

    // ---- load W fragments into registers (once); rows>=24 are zero ----
    const int r0 = mt*16 + g, r1 = r0 + 8;
    auto wv = [&](int r, int k) -> float {
        if (r >= 24) return 0.f;
        int gate = r >> 3, u = ublk + (r & 7);
        if (gate == 0) return Wh1[(size_t)k*UU + u];
        if (gate == 1) return Wh2[(size_t)k*UU + u];
        return Wha[(size_t)k*UU + u] + Whb[(size_t)k*UU + u];
    };
    uint32_t Afh[8][4], Afl[8][4];
#pragma unroll
    for (int j=0;j<8;j++) {
        const int kb = ks*128 + j*16 + tg*2;
        float w00 = wv(r0, kb),   w01 = wv(r0, kb+1);
        float w10 = wv(r1, kb),   w11 = wv(r1, kb+1);
        float w20 = wv(r0, kb+8), w21 = wv(r0, kb+9);
        float w30 = wv(r1, kb+8), w31 = wv(r1, kb+9);
        Afh[j][0] = pkbf(w00, w01); Afl[j][0] = pkbf(bflo(w00), bflo(w01));
        Afh[j][1] = pkbf(w10, w11); Afl[j][1] = pkbf(bflo(w10), bflo(w11));
        Afh[j][2] = pkbf(w20, w21); Afl[j][2] = pkbf(bflo(w20), bflo(w21));
        Afh[j][3] = pkbf(w30, w31); Afl[j][3] = pkbf(bflo(w30), bflo(w31));
    }

    // finalize mapping (tid < 64): (u-local 0..7, batch 0..7)
    const int ful = tid >> 3, fB = tid & 7;
    const int fug = ublk + ful;

    // xpre loader mapping (tid 128..191 -> slot 0..63)
    const int xw = tid - 128;
    const bool isldr = (xw >= 0 && xw < 64);
    const int xoff = isldr ? ((xw & 7)*UU + ublk + (xw >> 3)) : 0;

    // preload xpre(t=0) into sXP[0]
    if (isldr) {
        sXP[0][0][xw] = x1[xoff];
        sXP[0][1][xw] = x2[xoff];
        sXP[0][2][xw] = xab[xoff];
    }
    __syncthreads();

    const int rr0 = tid*2;

    for (int t = 0; t < TT; t++) {
        // ---- stage h into smem (hi/lo split) ----
        if (t == 0) {
            uint4 z = make_uint4(0,0,0,0);
            *reinterpret_cast<uint4*>(&sH[rr0*8])     = z;
            *reinterpret_cast<uint4*>(&sH[(rr0+1)*8]) = z;
            *reinterpret_cast<uint4*>(&sL[rr0*8])     = z;
            *reinterpret_cast<uint4*>(&sL[(rr0+1)*8]) = z;
        } else {
            const uint4* gp = reinterpret_cast<const uint4*>(&g_hu[t & 1][0]);
#pragma unroll
            for (int rr=0; rr<2; rr++) {
                uint4 q0 = __ldcg(gp + (rr0+rr)*2);
                uint4 q1 = __ldcg(gp + (rr0+rr)*2 + 1);
                uint4 hi, lo;
                hi.x = __byte_perm(q0.x, q0.y, 0x5410); hi.y = __byte_perm(q0.z, q0.w, 0x5410);
                hi.z = __byte_perm(q1.x, q1.y, 0x5410); hi.w = __byte_perm(q1.z, q1.w, 0x5410);
                lo.x = __byte_perm(q0.x, q0.y, 0x7632); lo.y = __byte_perm(q0.z, q0.w, 0x7632);
                lo.z = __byte_perm(q1.x, q1.y, 0x7632); lo.w = __byte_perm(q1.z, q1.w, 0x7632);
                *reinterpret_cast<uint4*>(&sH[(rr0+rr)*8]) = hi;
                *reinterpret_cast<uint4*>(&sL[(rr0+rr)*8]) = lo;
            }
        }
        __syncthreads();

        // loader group issues next step's xpre DRAM loads (hidden under MMA)
        float xv0, xv1, xv2;
        if (isldr && t+1 < TT) {
            const float* px = x1 + (size_t)(t+1)*(BB*UU) + xoff;
            xv0 = __ldcg(px);
            xv1 = __ldcg(x2  + (size_t)(t+1)*(BB*UU) + xoff);
            xv2 = __ldcg(xab + (size_t)(t+1)*(BB*UU) + xoff);
        }

        // ---- MMA phase: 3 independent accumulator chains ----
        float ac0[4] = {0.f,0.f,0.f,0.f};
        float ac1[4] = {0.f,0.f,0.f,0.f};
        float ac2[4] = {0.f,0.f,0.f,0.f};
        const int krow = ks*128 + (lane & 15);
#pragma unroll
        for (int j=0;j<8;j++) {
            uint32_t bh[2], bl[2];
            uint32_t off = (uint32_t)((krow + j*16) * 16);
            ldsm_x2t(bh, sHb + off);
            ldsm_x2t(bl, sLb + off);
            mma16816(ac0, Afh[j], bh);
            mma16816(ac1, Afl[j], bh);
            mma16816(ac2, Afh[j], bl);
        }
        float acc[4];
#pragma unroll
        for (int q=0;q<4;q++) acc[q] = (ac0[q] + ac1[q]) + ac2[q];
        *reinterpret_cast<float2*>(&part[mt][ks][g][tg*2])   = make_float2(acc[0], acc[1]);
        *reinterpret_cast<float2*>(&part[mt][ks][g+8][tg*2]) = make_float2(acc[2], acc[3]);
        __syncthreads();

        // loader group commits next step's xpre to smem (off critical path)
        if (isldr && t+1 < TT) {
            sXP[(t+1)&1][0][xw] = xv0;
            sXP[(t+1)&1][1][xw] = xv1;
            sXP[(t+1)&1][2][xw] = xv2;
        }

        // ---- finalize (64 threads) + release + hidden work + poll ----
        if (tid < 64) {
            float s0=0.f, s1=0.f, s2=0.f;
#pragma unroll
            for (int k6=0;k6<6;k6++) {
                s0 += part[0][k6][ful][fB];       // gate ff1 (rows 0..7)
                s1 += part[0][k6][8+ful][fB];     // gate ff2 (rows 8..15)
                s2 += part[1][k6][ful][fB];       // gate ta+tb (rows 16..23)
            }
            float p1  = sXP[t&1][0][tid];
            float p2  = sXP[t&1][1][tid];
            float pab = sXP[t&1][2][tid];
            float f1 = ftanh(s0 + p1), f2 = ftanh(s1 + p2);
            float ti = fsigm(s2 + pab);
            float hn = f1 + ti*(f2 - f1);
            float hl = bflo(hn);
            unsigned pk = ((uint32_t)__bfloat16_as_ushort(__float2bfloat16(hl)) << 16)
                        | __bfloat16_as_ushort(__float2bfloat16(hn));
            unsigned* dst = &g_hu[1-(t&1)][fug*8 + fB];
            asm volatile("st.global.cg.u32 [%0], %1;" :: "l"(dst), "r"(pk) : "memory");
            asm volatile("bar.sync 1, 64;" ::: "memory");   // all 64 h stores issued
            if (tid == 0) bar_red_release(&g_bar);
            // hidden under other CTAs' arrival:
            if (fug < DD) g_cfc[((size_t)fB*TT + t)*DD + fug] = hn;
            if (tid == 0 && t+1 < TT) {
                unsigned target = tbase + (unsigned)(t+1)*NSCAN;
                while (ld_acquire(&g_bar) < target) {}
            }
        }
        __syncthreads();
    }
}

// ---------------- LIF gate + residual add -----------------------------------
__global__ void lif_k(const float* __restrict__ thr_p,
                      const float* __restrict__ leak_p,
                      const float* __restrict__ steep_p) {
    int e = blockIdx.x*256 + threadIdx.x;
    int d = e & 511;
    float thr  = fabsf(thr_p[d]) * 0.1f;
    float leak = 1.f/(1.f + expf(-leak_p[d]));
    float sv = steep_p[d];
    float steep = (sv > 20.f) ? sv : log1pf(expf(sv));
    float c = g_cfc[e];
    float fire = 1.f/(1.f + expf(-steep*(fabsf(c) - thr)));
    float gate = fire + leak*(1.f - fire);
    g_x[e] += c*gate;
}

// ---------------- loss -------------------------------------------------------
__global__ void loss_k(const int* __restrict__ tgt, const float* __restrict__ logits) {
    int row  = blockIdx.x*8 + (threadIdx.x >> 5);
    int lane = threadIdx.x & 31;
    const float* lr = logits + (size_t)row*VV;
    float v[8]; float mx = -3.4e38f;
#pragma unroll
    for (int j=0;j<8;j++) { v[j] = lr[lane + 32*j]; mx = fmaxf(mx, v[j]); }
#pragma unroll
    for (int off=16; off; off>>=1) mx = fmaxf(mx, __shfl_xor_sync(0xffffffffu, mx, off));
    float se = 0.f;
#pragma unroll
    for (int j=0;j<8;j++) se += expf(v[j]-mx);
#pragma unroll
    for (int off=16; off; off>>=1) se += __shfl_xor_sync(0xffffffffu, se, off);
    if (lane == 0) {
        int tv = tgt[row];
        if (tv >= 0) {
            float nll = mx + logf(se) - lr[tv];
            atomicAdd(&g_loss[0], nll);
            atomicAdd(&g_loss[1], 1.f);
        }
    }
}

__global__ void fin_k(float* __restrict__ out, int out_size) {
    if (out_size > MM*VV) out[MM*VV] = g_loss[0]/g_loss[1];
}

// ---------------- driver ------------------------------------------------------
extern "C" void kernel_launch(void* const* d_in, const int* in_sizes, int n_in,
                              void* d_out, int out_size) {
    (void)in_sizes; (void)n_in;
    const int*   idx      = (const int*)  d_in[0];
    const int*   targets  = (const int*)  d_in[1];
    const float* wte      = (const float*)d_in[2];
    const float* ln1_s    = (const float*)d_in[3];
    const float* ln1_b    = (const float*)d_in[4];
    const float* Wff1     = (const float*)d_in[5];
    const float* bff1     = (const float*)d_in[6];
    const float* Wff2     = (const float*)d_in[7];
    const float* bff2     = (const float*)d_in[8];
    const float* Wta      = (const float*)d_in[9];
    const float* bta      = (const float*)d_in[10];
    const float* Wtb      = (const float*)d_in[11];
    const float* btb      = (const float*)d_in[12];
    const float* lif_thr  = (const float*)d_in[13];
    const float* lif_leak = (const float*)d_in[14];
    const float* lif_stp  = (const float*)d_in[15];
    const float* ln2_s    = (const float*)d_in[16];
    const float* ln2_b    = (const float*)d_in[17];
    const float* mW1      = (const float*)d_in[18];
    const float* mb1      = (const float*)d_in[19];
    const float* mW2      = (const float*)d_in[20];
    const float* mb2      = (const float*)d_in[21];
    const float* lnf_s    = (const float*)d_in[22];
    const float* lnf_b    = (const float*)d_in[23];
    float* out = (float*)d_out;

    cudaFuncSetAttribute(mm_gemm<0,true>,  cudaFuncAttributeMaxDynamicSharedMemorySize, GSMEM);
    cudaFuncSetAttribute(mm_gemm<2,false>, cudaFuncAttributeMaxDynamicSharedMemorySize, GSMEM);
    cudaFuncSetAttribute(mm_gemm<3,false>, cudaFuncAttributeMaxDynamicSharedMemorySize, GSMEM);
    cudaFuncSetAttribute(mm_gemm_p,        cudaFuncAttributeMaxDynamicSharedMemorySize, GSMEM);

    float *xp, *xpre;
    __nv_bfloat16 *ah1, *al1, *ah2, *al2, *wh, *wl, *wteh, *wtel;
    cudaGetSymbolAddress((void**)&xp,   g_x);
    cudaGetSymbolAddress((void**)&xpre, g_xpre);
    cudaGetSymbolAddress((void**)&ah1,  g_ah1);
    cudaGetSymbolAddress((void**)&al1,  g_al1);
    cudaGetSymbolAddress((void**)&ah2,  g_ah2);
    cudaGetSymbolAddress((void**)&al2,  g_al2);
    cudaGetSymbolAddress((void**)&wh,   g_wh);
    cudaGetSymbolAddress((void**)&wl,   g_wl);
    cudaGetSymbolAddress((void**)&wteh, g_wteh);
    cudaGetSymbolAddress((void**)&wtel, g_wtel);

    const size_t WSTRIDE = (size_t)(DD+UU)*UU;
    const size_t XG = (size_t)TT*BB*UU;

    for (int l = 0; l < LL; l++) {
        if (l == 0) {
            embln_k<<<MM/2, 256>>>(idx, wte, ln1_s, ln1_b, ah1, al1);    // launch 1
        } else {
            ln_bf_k<<<MM,128>>>(xp, ln1_s + l*DD, ln1_b + l*DD, ah1, al1);
        }
        cvt3_k<<<3*DD*UU/256, 256>>>(                                    // launch 2
            Wff1 + (size_t)l*WSTRIDE, Wff2 + (size_t)l*WSTRIDE,
            Wta  + (size_t)l*WSTRIDE, Wtb  + (size_t)l*WSTRIDE, wh, wl);
        mm_gemm_p<<<dim3(UU/128, MM/128, 3), 256, GSMEM>>>(              // launch 3
            ah1, al1, wh, wl,
            bff1 + l*UU, bff2 + l*UU, bta + l*UU, btb + l*UU, xpre);

        scan_k<<<NSCAN, 384>>>(                                          // launch 4 (ncu)
            Wff1 + (size_t)l*WSTRIDE + (size_t)DD*UU,
            Wff2 + (size_t)l*WSTRIDE + (size_t)DD*UU,
            Wta  + (size_t)l*WSTRIDE + (size_t)DD*UU,
            Wtb  + (size_t)l*WSTRIDE + (size_t)DD*UU,
            xpre, xpre + XG, xpre + 2*XG, l);

        lif_k<<<MM*DD/256, 256>>>(lif_thr + l*DD, lif_leak + l*DD, lif_stp + l*DD);

        ln_bf_k<<<MM,128>>>(xp, ln2_s + l*DD, ln2_b + l*DD, ah1, al1);
        cvt_e_k<<<DD*DFFC/256, 256>>>(mW1 + (size_t)l*DD*DFFC, wh, wl);
        mm_gemm<2,false><<<dim3(DFFC/128, MM/128), 256, GSMEM>>>(
            ah1, al1, wh, wl, mb1 + l*DFFC, nullptr,
            nullptr, ah2, al2, DFFC, DD);
        cvt_e_k<<<DFFC*DD/256, 256>>>(mW2 + (size_t)l*DFFC*DD, wh, wl);
        mm_gemm<3,false><<<dim3(DD/128, MM/128), 256, GSMEM>>>(
            ah2, al2, wh, wl, mb2 + l*DD, xp,
            xp, nullptr, nullptr, DD, DFFC);
    }

    ln_bf_k<<<MM,128>>>(xp, lnf_s, lnf_b, ah1, al1);
    cvt_e_k<<<VV*DD/256, 256>>>(wte, wteh, wtel);
    mm_gemm<0,true><<<dim3(VV/128, MM/128), 256, GSMEM>>>(
        ah1, al1, wteh, wtel, nullptr, nullptr,
        out, nullptr, nullptr, VV, DD);
    loss_k<<<MM/8, 256>>>(targets, out);
    fin_k<<<1,1>>>(out, out_size);
}

// round 15
// speedup vs baseline: 1.2100x; 1.1168x over previous
#include <cuda_runtime.h>
#include <cuda_bf16.h>
#include <math.h>
#include <cstdint>

#define BB 8
#define TT 4096
#define DD 512
#define UU 768
#define LL 4
#define VV 256
#define DFFC 2048
#define MM (BB*TT)          // 32768 rows
#define NSCAN 96            // persistent scan CTAs (8 u-cols each)

typedef unsigned long long ull;

// ---------------- PTX helpers ----------------------------------------------
__device__ __forceinline__ void bar_red_release(unsigned* p) {
    asm volatile("red.release.gpu.add.u32 [%0], 1;" :: "l"(p) : "memory");
}
__device__ __forceinline__ unsigned ld_acquire(const unsigned* p) {
    unsigned v;
    asm volatile("ld.acquire.gpu.u32 %0, [%1];" : "=r"(v) : "l"(p) : "memory");
    return v;
}
__device__ __forceinline__ uint32_t smem_u32(const void* p) {
    uint32_t a;
    asm("{ .reg .u64 t; cvta.to.shared.u64 t, %1; cvt.u32.u64 %0, t; }" : "=r"(a) : "l"(p));
    return a;
}
__device__ __forceinline__ void cpa16(uint32_t s, const void* g) {
    asm volatile("cp.async.cg.shared.global [%0], [%1], 16;" :: "r"(s), "l"(g));
}
__device__ __forceinline__ void cpa_commit() {
    asm volatile("cp.async.commit_group;" ::: "memory");
}
template<int N>
__device__ __forceinline__ void cpa_wait() {
    asm volatile("cp.async.wait_group %0;" :: "n"(N) : "memory");
}
__device__ __forceinline__ void ldsm_x4(uint32_t* r, uint32_t a) {
    asm volatile("ldmatrix.sync.aligned.m8n8.x4.shared.b16 {%0,%1,%2,%3}, [%4];"
        : "=r"(r[0]), "=r"(r[1]), "=r"(r[2]), "=r"(r[3]) : "r"(a));
}
__device__ __forceinline__ void ldsm_x4t(uint32_t* r, uint32_t a) {
    asm volatile("ldmatrix.sync.aligned.m8n8.x4.trans.shared.b16 {%0,%1,%2,%3}, [%4];"
        : "=r"(r[0]), "=r"(r[1]), "=r"(r[2]), "=r"(r[3]) : "r"(a));
}
__device__ __forceinline__ void ldsm_x2t(uint32_t* r, uint32_t a) {
    asm volatile("ldmatrix.sync.aligned.m8n8.x2.trans.shared.b16 {%0,%1}, [%2];"
        : "=r"(r[0]), "=r"(r[1]) : "r"(a));
}
__device__ __forceinline__ void mma16816(float* d, const uint32_t* a, const uint32_t* b) {
    asm volatile("mma.sync.aligned.m16n8k16.row.col.f32.bf16.bf16.f32 "
        "{%0,%1,%2,%3}, {%4,%5,%6,%7}, {%8,%9}, {%0,%1,%2,%3};"
        : "+f"(d[0]), "+f"(d[1]), "+f"(d[2]), "+f"(d[3])
        : "r"(a[0]), "r"(a[1]), "r"(a[2]), "r"(a[3]), "r"(b[0]), "r"(b[1]));
}
__device__ __forceinline__ uint32_t pkbf(float v0, float v1) {
    __nv_bfloat16 h0 = __float2bfloat16(v0), h1 = __float2bfloat16(v1);
    return ((uint32_t)__bfloat16_as_ushort(h1) << 16) | __bfloat16_as_ushort(h0);
}
__device__ __forceinline__ float bflo(float v) {
    return v - __bfloat162float(__float2bfloat16(v));
}
// fast transcendentals (MUFU ex2/rcp based; rel err ~1e-6)
__device__ __forceinline__ float ftanh(float x) {
    float e = __expf(2.f*x);
    return __fdividef(e - 1.f, e + 1.f);
}
__device__ __forceinline__ float fsigm(float x) {
    return __fdividef(1.f, 1.f + __expf(-x));
}

// ---------------- scratch ---------------------------------------------------
__device__ float g_x[MM*DD];
__device__ float g_xpre[3][TT*BB*UU];     // x1, x2, xab (fused a+b)
__device__ float g_cfc[MM*DD];
__device__ unsigned int g_hu[2][UU*BB];   // h as packed (bf16 hi | bf16 lo<<16), [k][b]
__device__ float g_loss[2];
__device__ unsigned int g_bar;            // monotonic across layers within a launch
__device__ __nv_bfloat16 g_ah1[MM*DD],  g_al1[MM*DD];
__device__ __nv_bfloat16 g_ah2[(size_t)MM*DFFC], g_al2[(size_t)MM*DFFC];
__device__ __nv_bfloat16 g_wh[4*DD*UU], g_wl[4*DD*UU];   // ≥ max(3*DD*UU, DFFC*DD)
__device__ __nv_bfloat16 g_wteh[VV*DD], g_wtel[VV*DD];

// ---------------- fused embed + LN1(layer0) + state reset --------------------
__global__ void embln_k(const int* __restrict__ idx, const float* __restrict__ wte,
                        const float* __restrict__ s, const float* __restrict__ b,
                        __nv_bfloat16* __restrict__ oh, __nv_bfloat16* __restrict__ ol) {
    __shared__ float red[2][8];
    if (blockIdx.x == 0 && threadIdx.x == 0) {
        g_bar = 0u; g_loss[0] = 0.f; g_loss[1] = 0.f;
    }
    const int half = threadIdx.x >> 7;
    const int wg   = threadIdx.x & 127;
    const int row  = blockIdx.x*2 + half;
    const int tok  = idx[row];
    float v[4]; float sum = 0.f, sq = 0.f;
#pragma unroll
    for (int j=0;j<4;j++) {
        v[j] = wte[(size_t)tok*DD + wg + j*128];
        g_x[(size_t)row*DD + wg + j*128] = v[j];
        sum += v[j]; sq += v[j]*v[j];
    }
#pragma unroll
    for (int off=16; off; off>>=1) {
        sum += __shfl_xor_sync(0xffffffffu, sum, off);
        sq  += __shfl_xor_sync(0xffffffffu, sq,  off);
    }
    int w = wg >> 5, lane = wg & 31;
    if (lane == 0) { red[half][w] = sum; }
    __syncthreads();
    if (lane == 1 && w == 0) {
        red[half][0] = red[half][0]+red[half][1]+red[half][2]+red[half][3];
    }
    __syncthreads();
    if (lane == 0) { red[half][4+w] = sq; }
    __syncthreads();
    if (lane == 1 && w == 0) {
        red[half][4] = red[half][4]+red[half][5]+red[half][6]+red[half][7];
    }
    __syncthreads();
    float mean = red[half][0]*(1.f/512.f);
    float var  = red[half][4]*(1.f/512.f) - mean*mean;
    float r = rsqrtf(var + 1e-5f);
#pragma unroll
    for (int j=0;j<4;j++) {
        int d = wg + j*128;
        float t = (v[j]-mean)*r*s[d] + b[d];
        __nv_bfloat16 h = __float2bfloat16(t);
        __nv_bfloat16 l = __float2bfloat16(t - __bfloat162float(h));
        oh[(size_t)row*DD + d] = h;
        ol[(size_t)row*DD + d] = l;
    }
}

// ---------------- layernorm -> bf16 hi/lo -----------------------------------
__global__ void ln_bf_k(const float* __restrict__ in, const float* __restrict__ s,
                        const float* __restrict__ b,
                        __nv_bfloat16* __restrict__ oh, __nv_bfloat16* __restrict__ ol) {
    __shared__ float red[8];
    int row = blockIdx.x;
    const float* x = in + (size_t)row*DD;
    float v[4]; float sum = 0.f, sq = 0.f;
#pragma unroll
    for (int j=0;j<4;j++) { v[j] = x[threadIdx.x + j*128]; sum += v[j]; sq += v[j]*v[j]; }
#pragma unroll
    for (int off=16; off; off>>=1) {
        sum += __shfl_xor_sync(0xffffffffu, sum, off);
        sq  += __shfl_xor_sync(0xffffffffu, sq,  off);
    }
    int w = threadIdx.x >> 5, lane = threadIdx.x & 31;
    if (lane == 0) { red[w] = sum; red[4+w] = sq; }
    __syncthreads();
    if (threadIdx.x == 0) {
        red[0] = red[0]+red[1]+red[2]+red[3];
        red[4] = red[4]+red[5]+red[6]+red[7];
    }
    __syncthreads();
    float mean = red[0]*(1.f/512.f);
    float var  = red[4]*(1.f/512.f) - mean*mean;
    float r = rsqrtf(var + 1e-5f);
#pragma unroll
    for (int j=0;j<4;j++) {
        int d = threadIdx.x + j*128;
        float t = (v[j]-mean)*r*s[d] + b[d];
        __nv_bfloat16 h = __float2bfloat16(t);
        __nv_bfloat16 l = __float2bfloat16(t - __bfloat162float(h));
        oh[(size_t)row*DD + d] = h;
        ol[(size_t)row*DD + d] = l;
    }
}

// ---------------- elementwise f32 -> bf16 hi/lo ------------------------------
__global__ void cvt_e_k(const float* __restrict__ X,
                        __nv_bfloat16* __restrict__ oh, __nv_bfloat16* __restrict__ ol) {
    int e = blockIdx.x*256 + threadIdx.x;
    float x = X[e];
    __nv_bfloat16 h = __float2bfloat16(x);
    __nv_bfloat16 l = __float2bfloat16(x - __bfloat162float(h));
    oh[e] = h; ol[e] = l;
}

// ---------------- fused 3-gate weight convert (gate2 = Wta+Wtb) --------------
__global__ void cvt3_k(const float* __restrict__ W0, const float* __restrict__ W1,
                       const float* __restrict__ W2a, const float* __restrict__ W2b,
                       __nv_bfloat16* __restrict__ oh, __nv_bfloat16* __restrict__ ol) {
    int e = blockIdx.x*256 + threadIdx.x;          // over 3*DD*UU
    int gate = e / (DD*UU);
    int off  = e - gate*(DD*UU);
    float x = (gate==0) ? W0[off] : (gate==1) ? W1[off] : (W2a[off] + W2b[off]);
    __nv_bfloat16 h = __float2bfloat16(x);
    __nv_bfloat16 l = __float2bfloat16(x - __bfloat162float(h));
    oh[e] = h; ol[e] = l;
}

// ---------------- bf16x3 tensor-core GEMM (mma.sync) — R7, unchanged --------
#define STG_BYTES 32768
#define GSMEM (2*STG_BYTES)

template<int EPI, bool BTR>
__global__ void __launch_bounds__(256) mm_gemm(
    const __nv_bfloat16* __restrict__ Ah, const __nv_bfloat16* __restrict__ Al,
    const __nv_bfloat16* __restrict__ Bh, const __nv_bfloat16* __restrict__ Bl,
    const float* __restrict__ bias, const float* __restrict__ R,
    float* __restrict__ Cf, __nv_bfloat16* __restrict__ Ch, __nv_bfloat16* __restrict__ Cl,
    int N, int K)
{
    extern __shared__ char sm[];
    const uint32_t sb = smem_u32(sm);
    const int tid = threadIdx.x, wid = tid >> 5, lane = tid & 31;
    const int wm = wid & 1, wn = wid >> 1;
    const int m0 = blockIdx.y << 7, n0 = blockIdx.x << 7;

    const int arow = tid >> 1, ac0 = (tid & 1) * 2;
    const int as   = (arow >> 1) & 3;
    const uint32_t aOff0 = (uint32_t)(arow*64 + ((ac0   ^ as) & 3)*16);
    const uint32_t aOff1 = (uint32_t)(arow*64 + (((ac0+1)^ as) & 3)*16);
    const int brow = tid >> 3, bc0 = (tid & 7) * 2;
    const uint32_t bOff0 = (uint32_t)(brow*256 + (((bc0  ) & 8) | (((bc0  ) ^ (brow&7)) & 7))*16);
    const uint32_t bOff1 = (uint32_t)(brow*256 + (((bc0+1) & 8) | (((bc0+1) ^ (brow&7)) & 7))*16);

    float acc[4][4][4];
#pragma unroll
    for (int i=0;i<4;i++)
#pragma unroll
        for (int j=0;j<4;j++)
#pragma unroll
            for (int q=0;q<4;q++) acc[i][j][q] = 0.f;

    const int NC = K >> 5;

    auto load_stage = [&](int c, int st) {
        const uint32_t s0 = sb + st*STG_BYTES;
        const int k0 = c << 5;
        {
            const __nv_bfloat16* ga = Ah + (size_t)(m0 + arow)*K + k0 + ac0*8;
            cpa16(s0 + aOff0, ga);
            cpa16(s0 + aOff1, ga + 8);
            const __nv_bfloat16* gl = Al + (size_t)(m0 + arow)*K + k0 + ac0*8;
            cpa16(s0 + 8192 + aOff0, gl);
            cpa16(s0 + 8192 + aOff1, gl + 8);
        }
        if (!BTR) {
            const __nv_bfloat16* gb = Bh + (size_t)(k0 + brow)*N + n0 + bc0*8;
            cpa16(s0 + 16384 + bOff0, gb);
            cpa16(s0 + 16384 + bOff1, gb + 8);
            const __nv_bfloat16* gl = Bl + (size_t)(k0 + brow)*N + n0 + bc0*8;
            cpa16(s0 + 24576 + bOff0, gl);
            cpa16(s0 + 24576 + bOff1, gl + 8);
        } else {
            const __nv_bfloat16* gb = Bh + (size_t)(n0 + arow)*K + k0 + ac0*8;
            cpa16(s0 + 16384 + aOff0, gb);
            cpa16(s0 + 16384 + aOff1, gb + 8);
            const __nv_bfloat16* gl = Bl + (size_t)(n0 + arow)*K + k0 + ac0*8;
            cpa16(s0 + 24576 + aOff0, gl);
            cpa16(s0 + 24576 + aOff1, gl + 8);
        }
        cpa_commit();
    };

    load_stage(0, 0);
    const int mat = lane >> 3, j8 = lane & 7;

    for (int c = 0; c < NC; c++) {
        if (c + 1 < NC) load_stage(c+1, (c+1)&1);
        if (c + 1 < NC) { cpa_wait<1>(); } else { cpa_wait<0>(); }
        __syncthreads();

        const uint32_t s0 = sb + (c&1)*STG_BYTES;
        const uint32_t sAh = s0, sAl = s0 + 8192, sBh = s0 + 16384, sBl = s0 + 24576;

#pragma unroll
        for (int k16 = 0; k16 < 2; k16++) {
            uint32_t fah[4][4], fal[4][4];
#pragma unroll
            for (int mi=0;mi<4;mi++) {
                int row = wm*64 + mi*16 + (mat&1)*8 + j8;
                int cc  = (k16*2 + (mat>>1)) ^ ((row>>1)&3);
                uint32_t off = (uint32_t)(row*64 + cc*16);
                ldsm_x4(fah[mi], sAh + off);
                ldsm_x4(fal[mi], sAl + off);
            }
            uint32_t fbh[4][2], fbl[4][2];
            if (!BTR) {
#pragma unroll
                for (int bi=0;bi<2;bi++) {
                    int row = k16*16 + (mat&1)*8 + j8;
                    int cn  = wn*4 + bi*2 + (mat>>1);
                    int cc  = (cn & 8) | ((cn ^ (row&7)) & 7);
                    uint32_t off = (uint32_t)(row*256 + cc*16);
                    uint32_t r4[4];
                    ldsm_x4t(r4, sBh + off);
                    fbh[2*bi][0]=r4[0]; fbh[2*bi][1]=r4[1]; fbh[2*bi+1][0]=r4[2]; fbh[2*bi+1][1]=r4[3];
                    ldsm_x4t(r4, sBl + off);
                    fbl[2*bi][0]=r4[0]; fbl[2*bi][1]=r4[1]; fbl[2*bi+1][0]=r4[2]; fbl[2*bi+1][1]=r4[3];
                }
            } else {
#pragma unroll
                for (int bi=0;bi<2;bi++) {
                    int row = wn*32 + bi*16 + (mat>>1)*8 + j8;
                    int cc  = (k16*2 + (mat&1)) ^ ((row>>1)&3);
                    uint32_t off = (uint32_t)(row*64 + cc*16);
                    uint32_t r4[4];
                    ldsm_x4(r4, sBh + off);
                    fbh[2*bi][0]=r4[0]; fbh[2*bi][1]=r4[1]; fbh[2*bi+1][0]=r4[2]; fbh[2*bi+1][1]=r4[3];
                    ldsm_x4(r4, sBl + off);
                    fbl[2*bi][0]=r4[0]; fbl[2*bi][1]=r4[1]; fbl[2*bi+1][0]=r4[2]; fbl[2*bi+1][1]=r4[3];
                }
            }
#pragma unroll
            for (int mi=0;mi<4;mi++)
#pragma unroll
                for (int ni=0;ni<4;ni++) {
                    mma16816(acc[mi][ni], fah[mi], fbh[ni]);
                    mma16816(acc[mi][ni], fal[mi], fbh[ni]);
                    mma16816(acc[mi][ni], fah[mi], fbl[ni]);
                }
        }
        __syncthreads();
    }

    const int lr = lane >> 2, lc = (lane & 3) * 2;
#pragma unroll
    for (int mi=0;mi<4;mi++) {
#pragma unroll
        for (int hh=0;hh<2;hh++) {
            const int m = m0 + wm*64 + mi*16 + hh*8 + lr;
#pragma unroll
            for (int ni=0;ni<4;ni++) {
                const int n = n0 + wn*32 + ni*8 + lc;
                float v0 = acc[mi][ni][2*hh], v1 = acc[mi][ni][2*hh+1];
                if (EPI != 0) { v0 += bias[n]; v1 += bias[n+1]; }
                if (EPI == 2) {
                    v0 = 0.5f*v0*(1.f + erff(v0*0.70710678118654752f));
                    v1 = 0.5f*v1*(1.f + erff(v1*0.70710678118654752f));
                    __nv_bfloat16 h0 = __float2bfloat16(v0);
                    __nv_bfloat16 h1 = __float2bfloat16(v1);
                    __nv_bfloat16 l0 = __float2bfloat16(v0 - __bfloat162float(h0));
                    __nv_bfloat16 l1 = __float2bfloat16(v1 - __bfloat162float(h1));
                    *reinterpret_cast<uint32_t*>(&Ch[(size_t)m*N + n]) =
                        ((uint32_t)__bfloat16_as_ushort(h1) << 16) | __bfloat16_as_ushort(h0);
                    *reinterpret_cast<uint32_t*>(&Cl[(size_t)m*N + n]) =
                        ((uint32_t)__bfloat16_as_ushort(l1) << 16) | __bfloat16_as_ushort(l0);
                } else if (EPI == 3) {
                    float2 r = *reinterpret_cast<const float2*>(&R[(size_t)m*N + n]);
                    *reinterpret_cast<float2*>(&Cf[(size_t)m*N + n]) =
                        make_float2(v0 + r.x, v1 + r.y);
                } else {
                    *reinterpret_cast<float2*>(&Cf[(size_t)m*N + n]) = make_float2(v0, v1);
                }
            }
        }
    }
}

// ---------------- fused projection GEMM (3 gates via blockIdx.z) -------------
__global__ void __launch_bounds__(256) mm_gemm_p(
    const __nv_bfloat16* __restrict__ Ah, const __nv_bfloat16* __restrict__ Al,
    const __nv_bfloat16* __restrict__ WhB, const __nv_bfloat16* __restrict__ WlB,
    const float* __restrict__ b0, const float* __restrict__ b1,
    const float* __restrict__ b2a, const float* __restrict__ b2b,
    float* __restrict__ xpre)
{
    extern __shared__ char sm[];
    const uint32_t sb = smem_u32(sm);
    const int tid = threadIdx.x, wid = tid >> 5, lane = tid & 31;
    const int wm = wid & 1, wn = wid >> 1;
    const int m0 = blockIdx.y << 7, n0 = blockIdx.x << 7;
    const int z  = blockIdx.z;
    const int N = UU, K = DD;
    const __nv_bfloat16* Bh = WhB + (size_t)z*DD*UU;
    const __nv_bfloat16* Bl = WlB + (size_t)z*DD*UU;
    float* Cf = xpre + (size_t)z*((size_t)TT*BB*UU);

    const int arow = tid >> 1, ac0 = (tid & 1) * 2;
    const int as   = (arow >> 1) & 3;
    const uint32_t aOff0 = (uint32_t)(arow*64 + ((ac0   ^ as) & 3)*16);
    const uint32_t aOff1 = (uint32_t)(arow*64 + (((ac0+1)^ as) & 3)*16);
    const int brow = tid >> 3, bc0 = (tid & 7) * 2;
    const uint32_t bOff0 = (uint32_t)(brow*256 + (((bc0  ) & 8) | (((bc0  ) ^ (brow&7)) & 7))*16);
    const uint32_t bOff1 = (uint32_t)(brow*256 + (((bc0+1) & 8) | (((bc0+1) ^ (brow&7)) & 7))*16);

    float acc[4][4][4];
#pragma unroll
    for (int i=0;i<4;i++)
#pragma unroll
        for (int j=0;j<4;j++)
#pragma unroll
            for (int q=0;q<4;q++) acc[i][j][q] = 0.f;

    const int NC = K >> 5;
    auto load_stage = [&](int c, int st) {
        const uint32_t s0 = sb + st*STG_BYTES;
        const int k0 = c << 5;
        const __nv_bfloat16* ga = Ah + (size_t)(m0 + arow)*K + k0 + ac0*8;
        cpa16(s0 + aOff0, ga);
        cpa16(s0 + aOff1, ga + 8);
        const __nv_bfloat16* gla = Al + (size_t)(m0 + arow)*K + k0 + ac0*8;
        cpa16(s0 + 8192 + aOff0, gla);
        cpa16(s0 + 8192 + aOff1, gla + 8);
        const __nv_bfloat16* gb = Bh + (size_t)(k0 + brow)*N + n0 + bc0*8;
        cpa16(s0 + 16384 + bOff0, gb);
        cpa16(s0 + 16384 + bOff1, gb + 8);
        const __nv_bfloat16* glb = Bl + (size_t)(k0 + brow)*N + n0 + bc0*8;
        cpa16(s0 + 24576 + bOff0, glb);
        cpa16(s0 + 24576 + bOff1, glb + 8);
        cpa_commit();
    };

    load_stage(0, 0);
    const int mat = lane >> 3, j8 = lane & 7;

    for (int c = 0; c < NC; c++) {
        if (c + 1 < NC) load_stage(c+1, (c+1)&1);
        if (c + 1 < NC) { cpa_wait<1>(); } else { cpa_wait<0>(); }
        __syncthreads();

        const uint32_t s0 = sb + (c&1)*STG_BYTES;
        const uint32_t sAh = s0, sAl = s0 + 8192, sBh = s0 + 16384, sBl = s0 + 24576;

#pragma unroll
        for (int k16 = 0; k16 < 2; k16++) {
            uint32_t fah[4][4], fal[4][4];
#pragma unroll
            for (int mi=0;mi<4;mi++) {
                int row = wm*64 + mi*16 + (mat&1)*8 + j8;
                int cc  = (k16*2 + (mat>>1)) ^ ((row>>1)&3);
                uint32_t off = (uint32_t)(row*64 + cc*16);
                ldsm_x4(fah[mi], sAh + off);
                ldsm_x4(fal[mi], sAl + off);
            }
            uint32_t fbh[4][2], fbl[4][2];
#pragma unroll
            for (int bi=0;bi<2;bi++) {
                int row = k16*16 + (mat&1)*8 + j8;
                int cn  = wn*4 + bi*2 + (mat>>1);
                int cc  = (cn & 8) | ((cn ^ (row&7)) & 7);
                uint32_t off = (uint32_t)(row*256 + cc*16);
                uint32_t r4[4];
                ldsm_x4t(r4, sBh + off);
                fbh[2*bi][0]=r4[0]; fbh[2*bi][1]=r4[1]; fbh[2*bi+1][0]=r4[2]; fbh[2*bi+1][1]=r4[3];
                ldsm_x4t(r4, sBl + off);
                fbl[2*bi][0]=r4[0]; fbl[2*bi][1]=r4[1]; fbl[2*bi+1][0]=r4[2]; fbl[2*bi+1][1]=r4[3];
            }
#pragma unroll
            for (int mi=0;mi<4;mi++)
#pragma unroll
                for (int ni=0;ni<4;ni++) {
                    mma16816(acc[mi][ni], fah[mi], fbh[ni]);
                    mma16816(acc[mi][ni], fal[mi], fbh[ni]);
                    mma16816(acc[mi][ni], fah[mi], fbl[ni]);
                }
        }
        __syncthreads();
    }

    const int lr = lane >> 2, lc = (lane & 3) * 2;
#pragma unroll
    for (int mi=0;mi<4;mi++) {
#pragma unroll
        for (int hh=0;hh<2;hh++) {
            const int m = m0 + wm*64 + mi*16 + hh*8 + lr;
#pragma unroll
            for (int ni=0;ni<4;ni++) {
                const int n = n0 + wn*32 + ni*8 + lc;
                float bn0 = (z==2) ? (b2a[n]   + b2b[n])   : (z==1 ? b1[n]   : b0[n]);
                float bn1 = (z==2) ? (b2a[n+1] + b2b[n+1]) : (z==1 ? b1[n+1] : b0[n+1]);
                float v0 = acc[mi][ni][2*hh]   + bn0;
                float v1 = acc[mi][ni][2*hh+1] + bn1;
                int b_ = m >> 12, t_ = m & 4095;
                *reinterpret_cast<float2*>(&Cf[(size_t)t_*(BB*UU) + b_*UU + n]) =
                    make_float2(v0, v1);
            }
        }
    }
}

// ---------------- persistent tensor-core CfC scan (96 CTAs, 8u, 3 gates) ----
// R15: warp-private h staging (each warp stages only its 128-row k-slice into
// its own 4KB smem region; __syncwarp instead of CTA-wide sync) — decouples
// warp stragglers at the most jitter-prone point. 2 CTA-wide syncs per step.
__global__ void __launch_bounds__(384, 1) scan_k(
    const float* __restrict__ Wh1, const float* __restrict__ Wh2,
    const float* __restrict__ Wha, const float* __restrict__ Whb,
    const float* __restrict__ x1,  const float* __restrict__ x2,
    const float* __restrict__ xab, int layer)
{
    // per-warp private slices: [warp][hi(1024 bf16) | lo(1024 bf16)]
    __shared__ __align__(16) __nv_bfloat16 sW[12][2048];
    __shared__ float part[2][6][16][8];                // [mt][ks][m][b]
    __shared__ float sXP[2][3][64];                    // double-buffered xpre stage

    const int tid  = threadIdx.x;
    const int wid  = tid >> 5, lane = tid & 31;
    const int mt   = wid & 1, ks = wid >> 1;
    const int ublk = blockIdx.x * 8;
    const int g    = lane >> 2, tg = lane & 3;
    const uint32_t sWb  = smem_u32(&sW[wid][0]);       // hi base (4KB slice: hi then lo)
    const uint32_t sWlb = sWb + 2048;                  // lo base (bytes: 1024*2)
    const unsigned tbase = (unsigned)layer * TT * NSCAN;

    // ---- load W fragments into registers (once); rows>=24 are zero ----
    const int r0 = mt*16 + g, r1 = r0 + 8;
    auto wv = [&](int r, int k) -> float {
        if (r >= 24) return 0.f;
        int gate = r >> 3, u = ublk + (r & 7);
        if (gate == 0) return Wh1[(size_t)k*UU + u];
        if (gate == 1) return Wh2[(size_t)k*UU + u];
        return Wha[(size_t)k*UU + u] + Whb[(size_t)k*UU + u];
    };
    uint32_t Afh[8][4], Afl[8][4];
#pragma unroll
    for (int j=0;j<8;j++) {
        const int kb = ks*128 + j*16 + tg*2;
        float w00 = wv(r0, kb),   w01 = wv(r0, kb+1);
        float w10 = wv(r1, kb),   w11 = wv(r1, kb+1);
        float w20 = wv(r0, kb+8), w21 = wv(r0, kb+9);
        float w30 = wv(r1, kb+8), w31 = wv(r1, kb+9);
        Afh[j][0] = pkbf(w00, w01); Afl[j][0] = pkbf(bflo(w00), bflo(w01));
        Afh[j][1] = pkbf(w10, w11); Afl[j][1] = pkbf(bflo(w10), bflo(w11));
        Afh[j][2] = pkbf(w20, w21); Afl[j][2] = pkbf(bflo(w20), bflo(w21));
        Afh[j][3] = pkbf(w30, w31); Afl[j][3] = pkbf(bflo(w30), bflo(w31));
    }

    // finalize mapping (tid < 64): (u-local 0..7, batch 0..7)
    const int ful = tid >> 3, fB = tid & 7;
    const int fug = ublk + ful;

    // xpre loader mapping (tid 128..191 -> slot 0..63)
    const int xw = tid - 128;
    const bool isldr = (xw >= 0 && xw < 64);
    const int xoff = isldr ? ((xw & 7)*UU + ublk + (xw >> 3)) : 0;

    // preload xpre(t=0) into sXP[0]
    if (isldr) {
        sXP[0][0][xw] = x1[xoff];
        sXP[0][1][xw] = x2[xoff];
        sXP[0][2][xw] = xab[xoff];
    }
    __syncthreads();

    // staging addressing (per warp): lane stages uint4 chunks of its slice.
    // word w = lane*4 + q*128 -> k_local = w/8 = lane/2 + q*16, b0 = (lane&1)*4.
    const int stKL = lane >> 1;            // + q*16
    const int stBH = lane & 1;             // half selector (b 0-3 vs 4-7)

    for (int t = 0; t < TT; t++) {
        // ---- warp-private h staging (no CTA-wide sync) ----
        if (t == 0) {
            uint2 z2 = make_uint2(0, 0);
#pragma unroll
            for (int q=0;q<8;q++) {
                int kl = stKL + q*16;
                uint32_t off = (uint32_t)(kl*16 + stBH*8);
                *reinterpret_cast<uint2*>(reinterpret_cast<char*>(&sW[wid][0]) + off) = z2;
                *reinterpret_cast<uint2*>(reinterpret_cast<char*>(&sW[wid][1024]) + off) = z2;
            }
        } else {
            const uint4* slice = reinterpret_cast<const uint4*>(&g_hu[t & 1][ks*1024]);
#pragma unroll
            for (int q=0;q<8;q++) {
                uint4 v = __ldcg(slice + lane + q*32);
                uint2 hi = make_uint2(__byte_perm(v.x, v.y, 0x5410),
                                      __byte_perm(v.z, v.w, 0x5410));
                uint2 lo = make_uint2(__byte_perm(v.x, v.y, 0x7632),
                                      __byte_perm(v.z, v.w, 0x7632));
                int kl = stKL + q*16;
                uint32_t off = (uint32_t)(kl*16 + stBH*8);
                *reinterpret_cast<uint2*>(reinterpret_cast<char*>(&sW[wid][0]) + off) = hi;
                *reinterpret_cast<uint2*>(reinterpret_cast<char*>(&sW[wid][1024]) + off) = lo;
            }
        }
        __syncwarp();

        // loader group issues next step's xpre DRAM loads (hidden under MMA)
        float xv0, xv1, xv2;
        if (isldr && t+1 < TT) {
            xv0 = __ldcg(x1  + (size_t)(t+1)*(BB*UU) + xoff);
            xv1 = __ldcg(x2  + (size_t)(t+1)*(BB*UU) + xoff);
            xv2 = __ldcg(xab + (size_t)(t+1)*(BB*UU) + xoff);
        }

        // ---- MMA phase: 3 independent accumulator chains ----
        float ac0[4] = {0.f,0.f,0.f,0.f};
        float ac1[4] = {0.f,0.f,0.f,0.f};
        float ac2[4] = {0.f,0.f,0.f,0.f};
        const int lrow = lane & 15;
#pragma unroll
        for (int j=0;j<8;j++) {
            uint32_t bh[2], bl[2];
            uint32_t off = (uint32_t)((lrow + j*16) * 16);
            ldsm_x2t(bh, sWb  + off);
            ldsm_x2t(bl, sWlb + off);
            mma16816(ac0, Afh[j], bh);
            mma16816(ac1, Afl[j], bh);
            mma16816(ac2, Afh[j], bl);
        }
        float acc[4];
#pragma unroll
        for (int q=0;q<4;q++) acc[q] = (ac0[q] + ac1[q]) + ac2[q];
        *reinterpret_cast<float2*>(&part[mt][ks][g][tg*2])   = make_float2(acc[0], acc[1]);
        *reinterpret_cast<float2*>(&part[mt][ks][g+8][tg*2]) = make_float2(acc[2], acc[3]);
        __syncthreads();    // sync A: part[] visible to finalize

        // loader group commits next step's xpre to smem (off critical path)
        if (isldr && t+1 < TT) {
            sXP[(t+1)&1][0][xw] = xv0;
            sXP[(t+1)&1][1][xw] = xv1;
            sXP[(t+1)&1][2][xw] = xv2;
        }

        // ---- finalize (64 threads) + release + hidden work + poll ----
        if (tid < 64) {
            float s0=0.f, s1=0.f, s2=0.f;
#pragma unroll
            for (int k6=0;k6<6;k6++) {
                s0 += part[0][k6][ful][fB];       // gate ff1 (rows 0..7)
                s1 += part[0][k6][8+ful][fB];     // gate ff2 (rows 8..15)
                s2 += part[1][k6][ful][fB];       // gate ta+tb (rows 16..23)
            }
            float p1  = sXP[t&1][0][tid];
            float p2  = sXP[t&1][1][tid];
            float pab = sXP[t&1][2][tid];
            float f1 = ftanh(s0 + p1), f2 = ftanh(s1 + p2);
            float ti = fsigm(s2 + pab);
            float hn = f1 + ti*(f2 - f1);
            float hl = bflo(hn);
            unsigned pk = ((uint32_t)__bfloat16_as_ushort(__float2bfloat16(hl)) << 16)
                        | __bfloat16_as_ushort(__float2bfloat16(hn));
            unsigned* dst = &g_hu[1-(t&1)][fug*8 + fB];
            asm volatile("st.global.cg.u32 [%0], %1;" :: "l"(dst), "r"(pk) : "memory");
            asm volatile("bar.sync 1, 64;" ::: "memory");   // all 64 h stores issued
            if (tid == 0) bar_red_release(&g_bar);
            // hidden under other CTAs' arrival:
            if (fug < DD) g_cfc[((size_t)fB*TT + t)*DD + fug] = hn;
            if (tid == 0 && t+1 < TT) {
                unsigned target = tbase + (unsigned)(t+1)*NSCAN;
                while (ld_acquire(&g_bar) < target) {}
            }
        }
        __syncthreads();    // sync B: poll broadcast + part[] WAR protection
    }
}

// ---------------- LIF gate + residual add -----------------------------------
__global__ void lif_k(const float* __restrict__ thr_p,
                      const float* __restrict__ leak_p,
                      const float* __restrict__ steep_p) {
    int e = blockIdx.x*256 + threadIdx.x;
    int d = e & 511;
    float thr  = fabsf(thr_p[d]) * 0.1f;
    float leak = 1.f/(1.f + expf(-leak_p[d]));
    float sv = steep_p[d];
    float steep = (sv > 20.f) ? sv : log1pf(expf(sv));
    float c = g_cfc[e];
    float fire = 1.f/(1.f + expf(-steep*(fabsf(c) - thr)));
    float gate = fire + leak*(1.f - fire);
    g_x[e] += c*gate;
}

// ---------------- loss -------------------------------------------------------
__global__ void loss_k(const int* __restrict__ tgt, const float* __restrict__ logits) {
    int row  = blockIdx.x*8 + (threadIdx.x >> 5);
    int lane = threadIdx.x & 31;
    const float* lr = logits + (size_t)row*VV;
    float v[8]; float mx = -3.4e38f;
#pragma unroll
    for (int j=0;j<8;j++) { v[j] = lr[lane + 32*j]; mx = fmaxf(mx, v[j]); }
#pragma unroll
    for (int off=16; off; off>>=1) mx = fmaxf(mx, __shfl_xor_sync(0xffffffffu, mx, off));
    float se = 0.f;
#pragma unroll
    for (int j=0;j<8;j++) se += expf(v[j]-mx);
#pragma unroll
    for (int off=16; off; off>>=1) se += __shfl_xor_sync(0xffffffffu, se, off);
    if (lane == 0) {
        int tv = tgt[row];
        if (tv >= 0) {
            float nll = mx + logf(se) - lr[tv];
            atomicAdd(&g_loss[0], nll);
            atomicAdd(&g_loss[1], 1.f);
        }
    }
}

__global__ void fin_k(float* __restrict__ out, int out_size) {
    if (out_size > MM*VV) out[MM*VV] = g_loss[0]/g_loss[1];
}

// ---------------- driver ------------------------------------------------------
extern "C" void kernel_launch(void* const* d_in, const int* in_sizes, int n_in,
                              void* d_out, int out_size) {
    (void)in_sizes; (void)n_in;
    const int*   idx      = (const int*)  d_in[0];
    const int*   targets  = (const int*)  d_in[1];
    const float* wte      = (const float*)d_in[2];
    const float* ln1_s    = (const float*)d_in[3];
    const float* ln1_b    = (const float*)d_in[4];
    const float* Wff1     = (const float*)d_in[5];
    const float* bff1     = (const float*)d_in[6];
    const float* Wff2     = (const float*)d_in[7];
    const float* bff2     = (const float*)d_in[8];
    const float* Wta      = (const float*)d_in[9];
    const float* bta      = (const float*)d_in[10];
    const float* Wtb      = (const float*)d_in[11];
    const float* btb      = (const float*)d_in[12];
    const float* lif_thr  = (const float*)d_in[13];
    const float* lif_leak = (const float*)d_in[14];
    const float* lif_stp  = (const float*)d_in[15];
    const float* ln2_s    = (const float*)d_in[16];
    const float* ln2_b    = (const float*)d_in[17];
    const float* mW1      = (const float*)d_in[18];
    const float* mb1      = (const float*)d_in[19];
    const float* mW2      = (const float*)d_in[20];
    const float* mb2      = (const float*)d_in[21];
    const float* lnf_s    = (const float*)d_in[22];
    const float* lnf_b    = (const float*)d_in[23];
    float* out = (float*)d_out;

    cudaFuncSetAttribute(mm_gemm<0,true>,  cudaFuncAttributeMaxDynamicSharedMemorySize, GSMEM);
    cudaFuncSetAttribute(mm_gemm<2,false>, cudaFuncAttributeMaxDynamicSharedMemorySize, GSMEM);
    cudaFuncSetAttribute(mm_gemm<3,false>, cudaFuncAttributeMaxDynamicSharedMemorySize, GSMEM);
    cudaFuncSetAttribute(mm_gemm_p,        cudaFuncAttributeMaxDynamicSharedMemorySize, GSMEM);

    float *xp, *xpre;
    __nv_bfloat16 *ah1, *al1, *ah2, *al2, *wh, *wl, *wteh, *wtel;
    cudaGetSymbolAddress((void**)&xp,   g_x);
    cudaGetSymbolAddress((void**)&xpre, g_xpre);
    cudaGetSymbolAddress((void**)&ah1,  g_ah1);
    cudaGetSymbolAddress((void**)&al1,  g_al1);
    cudaGetSymbolAddress((void**)&ah2,  g_ah2);
    cudaGetSymbolAddress((void**)&al2,  g_al2);
    cudaGetSymbolAddress((void**)&wh,   g_wh);
    cudaGetSymbolAddress((void**)&wl,   g_wl);
    cudaGetSymbolAddress((void**)&wteh, g_wteh);
    cudaGetSymbolAddress((void**)&wtel, g_wtel);

    const size_t WSTRIDE = (size_t)(DD+UU)*UU;
    const size_t XG = (size_t)TT*BB*UU;

    for (int l = 0; l < LL; l++) {
        if (l == 0) {
            embln_k<<<MM/2, 256>>>(idx, wte, ln1_s, ln1_b, ah1, al1);    // launch 1
        } else {
            ln_bf_k<<<MM,128>>>(xp, ln1_s + l*DD, ln1_b + l*DD, ah1, al1);
        }
        cvt3_k<<<3*DD*UU/256, 256>>>(                                    // launch 2
            Wff1 + (size_t)l*WSTRIDE, Wff2 + (size_t)l*WSTRIDE,
            Wta  + (size_t)l*WSTRIDE, Wtb  + (size_t)l*WSTRIDE, wh, wl);
        mm_gemm_p<<<dim3(UU/128, MM/128, 3), 256, GSMEM>>>(              // launch 3
            ah1, al1, wh, wl,
            bff1 + l*UU, bff2 + l*UU, bta + l*UU, btb + l*UU, xpre);

        scan_k<<<NSCAN, 384>>>(                                          // launch 4 (ncu)
            Wff1 + (size_t)l*WSTRIDE + (size_t)DD*UU,
            Wff2 + (size_t)l*WSTRIDE + (size_t)DD*UU,
            Wta  + (size_t)l*WSTRIDE + (size_t)DD*UU,
            Wtb  + (size_t)l*WSTRIDE + (size_t)DD*UU,
            xpre, xpre + XG, xpre + 2*XG, l);

        lif_k<<<MM*DD/256, 256>>>(lif_thr + l*DD, lif_leak + l*DD, lif_stp + l*DD);

        ln_bf_k<<<MM,128>>>(xp, ln2_s + l*DD, ln2_b + l*DD, ah1, al1);
        cvt_e_k<<<DD*DFFC/256, 256>>>(mW1 + (size_t)l*DD*DFFC, wh, wl);
        mm_gemm<2,false><<<dim3(DFFC/128, MM/128), 256, GSMEM>>>(
            ah1, al1, wh, wl, mb1 + l*DFFC, nullptr,
            nullptr, ah2, al2, DFFC, DD);
        cvt_e_k<<<DFFC*DD/256, 256>>>(mW2 + (size_t)l*DFFC*DD, wh, wl);
        mm_gemm<3,false><<<dim3(DD/128, MM/128), 256, GSMEM>>>(
            ah2, al2, wh, wl, mb2 + l*DD, xp,
            xp, nullptr, nullptr, DD, DFFC);
    }

    ln_bf_k<<<MM,128>>>(xp, lnf_s, lnf_b, ah1, al1);
    cvt_e_k<<<VV*DD/256, 256>>>(wte, wteh, wtel);
    mm_gemm<0,true><<<dim3(VV/128, MM/128), 256, GSMEM>>>(
        ah1, al1, wteh, wtel, nullptr, nullptr,
        out, nullptr, nullptr, VV, DD);
    loss_k<<<MM/8, 256>>>(targets, out);
    fin_k<<<1,1>>>(out, out_size);
}